// round 2
// baseline (speedup 1.0000x reference)
#include <cuda_runtime.h>
#include <cstdint>
#include <cstddef>

#define T_SEQ 1024
#define BSZ   8
#define EMB   1024
#define NH    16
#define HD    64
#define NR    33
#define E3    (3*EMB)
#define SCALE 0.125f
#define BH    (BSZ*NH)

// ---- scratch (static device globals; no allocations allowed) ----
__device__ float g_qkv[(size_t)T_SEQ * BSZ * E3];          // 96 MB  [T,B,3E]
__device__ float g_scores[(size_t)BH * T_SEQ * T_SEQ];     // 512 MB [BH,T,S]
__device__ float g_qrel[(size_t)BH * T_SEQ * NR];          // 16.5 MB
__device__ float g_attn[(size_t)T_SEQ * BSZ * EMB];        // 32 MB  [T,B,E]

// ============================================================
// Generic C[M,N] = A[M,K] @ W[N,K]^T + bias[N]
// 64x64 tile, 256 threads, 4x4 per thread, BK=16.
// Requires M%64==0, N%64==0, K%16==0 (true for all our calls).
// ============================================================
__global__ void __launch_bounds__(256)
gemm_abt64(const float* __restrict__ A,
           const float* __restrict__ W,
           const float* __restrict__ bias,
           float* __restrict__ C,
           int M, int N, int K) {
    __shared__ float As[16][64];
    __shared__ float Bs[16][64];
    const int tid = threadIdx.x;
    const int tx = tid & 15, ty = tid >> 4;
    const int row0 = blockIdx.y * 64, col0 = blockIdx.x * 64;
    const int lr = tid >> 2;          // 0..63
    const int lk = (tid & 3) * 4;     // 0,4,8,12

    float acc[4][4] = {};
    for (int k0 = 0; k0 < K; k0 += 16) {
        float4 a = *(const float4*)&A[(size_t)(row0 + lr) * K + k0 + lk];
        float4 b = *(const float4*)&W[(size_t)(col0 + lr) * K + k0 + lk];
        As[lk + 0][lr] = a.x; As[lk + 1][lr] = a.y; As[lk + 2][lr] = a.z; As[lk + 3][lr] = a.w;
        Bs[lk + 0][lr] = b.x; Bs[lk + 1][lr] = b.y; Bs[lk + 2][lr] = b.z; Bs[lk + 3][lr] = b.w;
        __syncthreads();
        #pragma unroll
        for (int kk = 0; kk < 16; kk++) {
            float ar[4], br[4];
            *(float4*)ar = *(const float4*)&As[kk][ty * 4];
            *(float4*)br = *(const float4*)&Bs[kk][tx * 4];
            #pragma unroll
            for (int i = 0; i < 4; i++)
                #pragma unroll
                for (int j = 0; j < 4; j++)
                    acc[i][j] += ar[i] * br[j];
        }
        __syncthreads();
    }
    #pragma unroll
    for (int i = 0; i < 4; i++) {
        #pragma unroll
        for (int j = 0; j < 4; j++) {
            int n = col0 + tx * 4 + j;
            C[(size_t)(row0 + ty * 4 + i) * N + n] = acc[i][j] + bias[n];
        }
    }
}

// ============================================================
// qrel[bh, t, r] = SCALE * sum_j q[t,b,h*64+j] * rpk[r, j]
// one block per (t, bh); 128 threads
// ============================================================
__global__ void __launch_bounds__(128)
qrel_kernel(const float* __restrict__ rpk) {
    const int t = blockIdx.x;
    const int bh = blockIdx.y;
    const int b = bh >> 4, h = bh & 15;
    __shared__ float qs[HD];
    __shared__ float rs[NR * HD];
    const int tid = threadIdx.x;
    if (tid < HD)
        qs[tid] = g_qkv[(size_t)t * BSZ * E3 + (size_t)b * E3 + h * HD + tid] * SCALE;
    for (int i = tid; i < NR * HD; i += 128) rs[i] = rpk[i];
    __syncthreads();
    if (tid < NR) {
        float s = 0.f;
        #pragma unroll
        for (int j = 0; j < HD; j++) s += qs[j] * rs[tid * HD + j];
        g_qrel[((size_t)bh * T_SEQ + t) * NR + tid] = s;
    }
}

// ============================================================
// scores[bh,t,s] = SCALE * q[t]·k[s] + qrel[bh,t,clip(s-t)+16]
// 64x64 tile over (t,s); K=64 (full head dim); batched over bh.
// ============================================================
__global__ void __launch_bounds__(256)
scores_kernel() {
    const int bh = blockIdx.z;
    const int b = bh >> 4, h = bh & 15;
    const int t0 = blockIdx.y * 64, s0 = blockIdx.x * 64;
    __shared__ float Qs[64][64];   // [j][t]
    __shared__ float Ks[64][64];   // [j][s]
    const int tid = threadIdx.x;
    const int tx = tid & 15, ty = tid >> 4;
    const size_t qoff = (size_t)b * E3 + h * HD;
    const int lr = tid >> 2;       // 0..63
    const int lf = tid & 3;

    #pragma unroll
    for (int i = 0; i < 4; i++) {
        int c = (lf + i * 4) * 4;  // 0..60 step 4
        float4 q = *(const float4*)&g_qkv[(size_t)(t0 + lr) * BSZ * E3 + qoff + c];
        float4 k = *(const float4*)&g_qkv[(size_t)(s0 + lr) * BSZ * E3 + qoff + EMB + c];
        Qs[c + 0][lr] = q.x * SCALE; Qs[c + 1][lr] = q.y * SCALE;
        Qs[c + 2][lr] = q.z * SCALE; Qs[c + 3][lr] = q.w * SCALE;
        Ks[c + 0][lr] = k.x; Ks[c + 1][lr] = k.y;
        Ks[c + 2][lr] = k.z; Ks[c + 3][lr] = k.w;
    }
    __syncthreads();

    float acc[4][4] = {};
    #pragma unroll 16
    for (int j = 0; j < 64; j++) {
        float qr[4], kr[4];
        *(float4*)qr = *(const float4*)&Qs[j][ty * 4];
        *(float4*)kr = *(const float4*)&Ks[j][tx * 4];
        #pragma unroll
        for (int i = 0; i < 4; i++)
            #pragma unroll
            for (int jj = 0; jj < 4; jj++)
                acc[i][jj] += qr[i] * kr[jj];
    }

    #pragma unroll
    for (int i = 0; i < 4; i++) {
        int t = t0 + ty * 4 + i;
        const float* qr_row = &g_qrel[((size_t)bh * T_SEQ + t) * NR];
        #pragma unroll
        for (int jj = 0; jj < 4; jj++) {
            int s = s0 + tx * 4 + jj;
            int d = s - t;
            d = d < -16 ? -16 : (d > 16 ? 16 : d);
            g_scores[((size_t)bh * T_SEQ + t) * T_SEQ + s] = acc[i][jj] + qr_row[d + 16];
        }
    }
}

// ============================================================
// in-place row softmax over last dim (S=1024), one block per row
// ============================================================
__global__ void __launch_bounds__(256)
softmax_kernel() {
    const size_t row = blockIdx.x;
    float* p = g_scores + row * (size_t)T_SEQ;
    const int tid = threadIdx.x;       // 256
    float4 v = *(float4*)(p + tid * 4);

    __shared__ float red[8];
    __shared__ float bM, bS;

    float m = fmaxf(fmaxf(v.x, v.y), fmaxf(v.z, v.w));
    #pragma unroll
    for (int o = 16; o; o >>= 1) m = fmaxf(m, __shfl_xor_sync(0xffffffffu, m, o));
    if ((tid & 31) == 0) red[tid >> 5] = m;
    __syncthreads();
    if (tid == 0) {
        float x = red[0];
        #pragma unroll
        for (int i = 1; i < 8; i++) x = fmaxf(x, red[i]);
        bM = x;
    }
    __syncthreads();
    const float M = bM;

    v.x = __expf(v.x - M); v.y = __expf(v.y - M);
    v.z = __expf(v.z - M); v.w = __expf(v.w - M);
    float s = v.x + v.y + v.z + v.w;
    #pragma unroll
    for (int o = 16; o; o >>= 1) s += __shfl_xor_sync(0xffffffffu, s, o);
    if ((tid & 31) == 0) red[tid >> 5] = s;
    __syncthreads();
    if (tid == 0) {
        float x = 0.f;
        #pragma unroll
        for (int i = 0; i < 8; i++) x += red[i];
        bS = x;
    }
    __syncthreads();
    const float inv = 1.0f / bS;

    v.x *= inv; v.y *= inv; v.z *= inv; v.w *= inv;
    *(float4*)(p + tid * 4) = v;
}

// ============================================================
// avg_w[b,t,s] = mean_h p[b*16+h, t, s]   (float4 vectorized)
// ============================================================
__global__ void __launch_bounds__(256)
avgw_kernel(float* __restrict__ avg) {
    size_t i4 = (size_t)blockIdx.x * blockDim.x + threadIdx.x;  // B*T*T/4 threads
    size_t i = i4 * 4;
    int s = (int)(i & (T_SEQ - 1));
    size_t bt = i >> 10;
    int t = (int)(bt & (T_SEQ - 1));
    int b = (int)(bt >> 10);
    float4 acc = make_float4(0.f, 0.f, 0.f, 0.f);
    const size_t base = (((size_t)(b * NH)) * T_SEQ + t) * T_SEQ + s;
    #pragma unroll
    for (int h = 0; h < NH; h++) {
        float4 v = *(const float4*)&g_scores[base + (size_t)h * T_SEQ * T_SEQ];
        acc.x += v.x; acc.y += v.y; acc.z += v.z; acc.w += v.w;
    }
    const float inv = 1.0f / NH;
    acc.x *= inv; acc.y *= inv; acc.z *= inv; acc.w *= inv;
    *(float4*)&avg[i] = acc;
}

// ============================================================
// attn[t, b, h*64+j] = sum_s p[bh,t,s] * v[s,b,h*64+j]
// 64(t) x 64(j) tile, BK=32, batched over bh
// ============================================================
__global__ void __launch_bounds__(256)
pv_kernel() {
    const int bh = blockIdx.z;
    const int b = bh >> 4, h = bh & 15;
    const int t0 = blockIdx.x * 64;
    __shared__ float Ps[32][64];   // [s][t]
    __shared__ float Vs[32][64];   // [s][j]
    const int tid = threadIdx.x;
    const int tx = tid & 15, ty = tid >> 4;
    const size_t pbase = (size_t)bh * T_SEQ * T_SEQ;
    const size_t vbase = (size_t)b * E3 + 2 * EMB + h * HD;

    float acc[4][4] = {};
    for (int s0 = 0; s0 < T_SEQ; s0 += 32) {
        {   // load P tile transposed: rows t0..t0+63, cols s0..s0+31
            int lr = tid >> 2;       // t: 0..63
            int lf = tid & 3;
            #pragma unroll
            for (int i = 0; i < 2; i++) {
                int c = (lf + i * 4) * 4;   // 0..28
                float4 pv4 = *(const float4*)&g_scores[pbase + (size_t)(t0 + lr) * T_SEQ + s0 + c];
                Ps[c + 0][lr] = pv4.x; Ps[c + 1][lr] = pv4.y;
                Ps[c + 2][lr] = pv4.z; Ps[c + 3][lr] = pv4.w;
            }
        }
        {   // load V tile: rows s0..s0+31, 64 cols
            int lr = tid >> 3;       // s: 0..31
            int lf = tid & 7;
            #pragma unroll
            for (int i = 0; i < 2; i++) {
                int c = (lf + i * 8) * 4;   // 0..60
                float4 vv = *(const float4*)&g_qkv[(size_t)(s0 + lr) * BSZ * E3 + vbase + c];
                *(float4*)&Vs[lr][c] = vv;
            }
        }
        __syncthreads();
        #pragma unroll
        for (int kk = 0; kk < 32; kk++) {
            float pr[4], vr[4];
            *(float4*)pr = *(const float4*)&Ps[kk][ty * 4];
            *(float4*)vr = *(const float4*)&Vs[kk][tx * 4];
            #pragma unroll
            for (int i = 0; i < 4; i++)
                #pragma unroll
                for (int j = 0; j < 4; j++)
                    acc[i][j] += pr[i] * vr[j];
        }
        __syncthreads();
    }
    #pragma unroll
    for (int i = 0; i < 4; i++)
        #pragma unroll
        for (int j = 0; j < 4; j++)
            g_attn[(size_t)(t0 + ty * 4 + i) * BSZ * EMB + (size_t)b * EMB + h * HD + tx * 4 + j]
                = acc[i][j];
}

// ============================================================
extern "C" void kernel_launch(void* const* d_in, const int* in_sizes, int n_in,
                              void* d_out, int out_size) {
    const float* query = (const float*)d_in[0];
    const float* w_in  = (const float*)d_in[1];
    const float* b_in  = (const float*)d_in[2];
    const float* w_out = (const float*)d_in[3];
    const float* b_out = (const float*)d_in[4];
    const float* rpk   = (const float*)d_in[5];
    float* out = (float*)d_out;

    void *p_qkv_v, *p_attn_v;
    cudaGetSymbolAddress(&p_qkv_v, g_qkv);
    cudaGetSymbolAddress(&p_attn_v, g_attn);
    float* p_qkv = (float*)p_qkv_v;
    float* p_attn = (float*)p_attn_v;

    // 1. QKV projection: [8192,1024] @ [3072,1024]^T
    {
        dim3 grid(E3 / 64, (T_SEQ * BSZ) / 64);
        gemm_abt64<<<grid, 256>>>(query, w_in, b_in, p_qkv, T_SEQ * BSZ, E3, EMB);
    }
    // 2. qrel table
    {
        dim3 grid(T_SEQ, BH);
        qrel_kernel<<<grid, 128>>>(rpk);
    }
    // 3. scores = scaled q·k + qrel lookup
    {
        dim3 grid(T_SEQ / 64, T_SEQ / 64, BH);
        scores_kernel<<<grid, 256>>>();
    }
    // 4. softmax in place
    softmax_kernel<<<(unsigned)(BH * T_SEQ), 256>>>();
    // 5. averaged weights (second output)
    if (out_size >= 2 * T_SEQ * BSZ * EMB) {
        size_t n4 = (size_t)BSZ * T_SEQ * T_SEQ / 4;
        avgw_kernel<<<(unsigned)(n4 / 256), 256>>>(out + (size_t)T_SEQ * BSZ * EMB);
    }
    // 6. attn = p @ v
    {
        dim3 grid(T_SEQ / 64, 1, BH);
        pv_kernel<<<grid, 256>>>();
    }
    // 7. out projection -> first chunk of d_out
    {
        dim3 grid(EMB / 64, (T_SEQ * BSZ) / 64);
        gemm_abt64<<<grid, 256>>>(p_attn, w_out, b_out, out, T_SEQ * BSZ, EMB, EMB);
    }
}

// round 3
// speedup vs baseline: 1.2678x; 1.2678x over previous
#include <cuda_runtime.h>
#include <cstdint>
#include <cstddef>

#define T_SEQ 1024
#define BSZ   8
#define EMB   1024
#define NH    16
#define HD    64
#define NR    33
#define E3    (3*EMB)
#define SCALE 0.125f
#define BH    (BSZ*NH)

// ---- scratch (static device globals; no allocations allowed) ----
__device__ float g_qkv[(size_t)T_SEQ * BSZ * E3];          // 96 MB  [T,B,3E]
__device__ float g_scores[(size_t)BH * T_SEQ * T_SEQ];     // 512 MB [BH,T,S]
__device__ float g_qrel[(size_t)BH * T_SEQ * NR];          // 16.5 MB
__device__ float g_attn[(size_t)T_SEQ * BSZ * EMB];        // 32 MB  [T,B,E]

// ============================================================
// C[M,N] = A[M,K] @ W[N,K]^T + bias[N]
// 128x128 tile, BK=16, 256 threads, 8x8 microtile, double-buffered.
// Requires M%128==0, N%128==0, K%16==0.
// ============================================================
__global__ void __launch_bounds__(256)
gemm128(const float* __restrict__ A, const float* __restrict__ W,
        const float* __restrict__ bias, float* __restrict__ C,
        int M, int N, int K) {
    __shared__ float As[2][16][132];
    __shared__ float Bs[2][16][132];
    const int tid = threadIdx.x;
    const int tx = tid & 15, ty = tid >> 4;
    const int row0 = blockIdx.y * 128, col0 = blockIdx.x * 128;
    const int lr0 = tid >> 2;        // 0..63
    const int lk  = (tid & 3) * 4;   // 0,4,8,12

    const float* Ab = A + (size_t)row0 * K;
    const float* Wb = W + (size_t)col0 * K;

    float4 pa0, pa1, pb0, pb1;

#define G128_FETCH(k0)                                                    \
    pa0 = *(const float4*)&Ab[(size_t)lr0 * K + (k0) + lk];               \
    pa1 = *(const float4*)&Ab[(size_t)(lr0 + 64) * K + (k0) + lk];        \
    pb0 = *(const float4*)&Wb[(size_t)lr0 * K + (k0) + lk];               \
    pb1 = *(const float4*)&Wb[(size_t)(lr0 + 64) * K + (k0) + lk];

#define G128_STORE(bf)                                                    \
    As[bf][lk+0][lr0]=pa0.x; As[bf][lk+1][lr0]=pa0.y;                     \
    As[bf][lk+2][lr0]=pa0.z; As[bf][lk+3][lr0]=pa0.w;                     \
    As[bf][lk+0][lr0+64]=pa1.x; As[bf][lk+1][lr0+64]=pa1.y;               \
    As[bf][lk+2][lr0+64]=pa1.z; As[bf][lk+3][lr0+64]=pa1.w;               \
    Bs[bf][lk+0][lr0]=pb0.x; Bs[bf][lk+1][lr0]=pb0.y;                     \
    Bs[bf][lk+2][lr0]=pb0.z; Bs[bf][lk+3][lr0]=pb0.w;                     \
    Bs[bf][lk+0][lr0+64]=pb1.x; Bs[bf][lk+1][lr0+64]=pb1.y;               \
    Bs[bf][lk+2][lr0+64]=pb1.z; Bs[bf][lk+3][lr0+64]=pb1.w;

#define G128_COMPUTE(bf)                                                  \
    _Pragma("unroll")                                                     \
    for (int kk = 0; kk < 16; kk++) {                                     \
        float ar[8], br[8];                                               \
        *(float4*)ar       = *(const float4*)&As[bf][kk][ty * 8];         \
        *(float4*)(ar + 4) = *(const float4*)&As[bf][kk][ty * 8 + 4];     \
        *(float4*)br       = *(const float4*)&Bs[bf][kk][tx * 8];         \
        *(float4*)(br + 4) = *(const float4*)&Bs[bf][kk][tx * 8 + 4];     \
        _Pragma("unroll")                                                 \
        for (int i = 0; i < 8; i++)                                       \
            _Pragma("unroll")                                             \
            for (int j = 0; j < 8; j++)                                   \
                acc[i][j] += ar[i] * br[j];                               \
    }

    float acc[8][8] = {};
    G128_FETCH(0)
    G128_STORE(0)
    __syncthreads();
    int buf = 0;
    for (int k0 = 16; k0 < K; k0 += 16) {
        G128_FETCH(k0)
        G128_COMPUTE(buf)
        __syncthreads();
        G128_STORE(buf ^ 1)
        __syncthreads();
        buf ^= 1;
    }
    G128_COMPUTE(buf)

    #pragma unroll
    for (int i = 0; i < 8; i++) {
        const size_t r = (size_t)(row0 + ty * 8 + i) * N;
        #pragma unroll
        for (int j = 0; j < 8; j += 4) {
            int n = col0 + tx * 8 + j;
            float4 o;
            o.x = acc[i][j + 0] + bias[n + 0];
            o.y = acc[i][j + 1] + bias[n + 1];
            o.z = acc[i][j + 2] + bias[n + 2];
            o.w = acc[i][j + 3] + bias[n + 3];
            *(float4*)&C[r + n] = o;
        }
    }
}

// ============================================================
// qrel[bh, t, r] = SCALE * sum_j q[t,b,h*64+j] * rpk[r, j]
// ============================================================
__global__ void __launch_bounds__(128)
qrel_kernel(const float* __restrict__ rpk) {
    const int t = blockIdx.x;
    const int bh = blockIdx.y;
    const int b = bh >> 4, h = bh & 15;
    __shared__ float qs[HD];
    __shared__ float rs[NR * HD];
    const int tid = threadIdx.x;
    if (tid < HD)
        qs[tid] = g_qkv[(size_t)t * BSZ * E3 + (size_t)b * E3 + h * HD + tid] * SCALE;
    for (int i = tid; i < NR * HD; i += 128) rs[i] = rpk[i];
    __syncthreads();
    if (tid < NR) {
        float s = 0.f;
        #pragma unroll
        for (int j = 0; j < HD; j++) s += qs[j] * rs[tid * HD + j];
        g_qrel[((size_t)bh * T_SEQ + t) * NR + tid] = s;
    }
}

// ============================================================
// scores[bh,t,s] = SCALE*q[t]·k[s] + qrel[bh,t,clip(s-t)+16]
// 128x128 tile over (t,s); K=64; 8x8 microtile; dynamic smem 67.6KB
// ============================================================
__global__ void __launch_bounds__(256)
scores_kernel() {
    extern __shared__ float dyn[];
    float (*Qs)[132] = (float(*)[132])dyn;               // [64][132]  [j][t]
    float (*Ks)[132] = (float(*)[132])(dyn + 64 * 132);  // [64][132]  [j][s]

    const int bh = blockIdx.z;
    const int b = bh >> 4, h = bh & 15;
    const int t0 = blockIdx.y * 128, s0 = blockIdx.x * 128;
    const int tid = threadIdx.x;
    const int tx = tid & 15, ty = tid >> 4;
    const size_t qoff = (size_t)b * E3 + h * HD;

    #pragma unroll
    for (int i = 0; i < 8; i++) {
        int f = tid + i * 256;
        int row = f >> 4;           // 0..127
        int c = (f & 15) * 4;       // 0..60
        float4 q = *(const float4*)&g_qkv[(size_t)(t0 + row) * BSZ * E3 + qoff + c];
        float4 k = *(const float4*)&g_qkv[(size_t)(s0 + row) * BSZ * E3 + qoff + EMB + c];
        Qs[c + 0][row] = q.x * SCALE; Qs[c + 1][row] = q.y * SCALE;
        Qs[c + 2][row] = q.z * SCALE; Qs[c + 3][row] = q.w * SCALE;
        Ks[c + 0][row] = k.x; Ks[c + 1][row] = k.y;
        Ks[c + 2][row] = k.z; Ks[c + 3][row] = k.w;
    }
    __syncthreads();

    float acc[8][8] = {};
    #pragma unroll 16
    for (int j = 0; j < 64; j++) {
        float qr[8], kr[8];
        *(float4*)qr       = *(const float4*)&Qs[j][ty * 8];
        *(float4*)(qr + 4) = *(const float4*)&Qs[j][ty * 8 + 4];
        *(float4*)kr       = *(const float4*)&Ks[j][tx * 8];
        *(float4*)(kr + 4) = *(const float4*)&Ks[j][tx * 8 + 4];
        #pragma unroll
        for (int i = 0; i < 8; i++)
            #pragma unroll
            for (int jj = 0; jj < 8; jj++)
                acc[i][jj] += qr[i] * kr[jj];
    }

    #pragma unroll
    for (int i = 0; i < 8; i++) {
        int t = t0 + ty * 8 + i;
        const float* qr_row = &g_qrel[((size_t)bh * T_SEQ + t) * NR];
        float* orow = &g_scores[((size_t)bh * T_SEQ + t) * T_SEQ];
        #pragma unroll
        for (int jj = 0; jj < 8; jj++) {
            int s = s0 + tx * 8 + jj;
            int d = s - t;
            d = d < -16 ? -16 : (d > 16 ? 16 : d);
            orow[s] = acc[i][jj] + qr_row[d + 16];
        }
    }
}

// ============================================================
// Fused softmax (in place) + head-averaged weights.
// One block per (t, b): 16 head-rows of length 1024.
// Warp w handles rows h=w and h=w+8. Dynamic smem 64.3KB.
// ============================================================
#define SMPAD 1028
__global__ void __launch_bounds__(256)
softmax_avg_kernel(float* __restrict__ avg) {
    extern __shared__ float S[];    // [16][SMPAD]
    const int t = blockIdx.x;
    const int b = blockIdx.y;
    const int tid = threadIdx.x;
    const int warp = tid >> 5, lane = tid & 31;

    #pragma unroll
    for (int rep = 0; rep < 2; rep++) {
        const int h = warp + rep * 8;
        float* row = g_scores + (((size_t)(b * NH + h)) * T_SEQ + t) * T_SEQ;
        float4 v[8];
        #pragma unroll
        for (int i = 0; i < 8; i++)
            v[i] = *(const float4*)&row[lane * 4 + i * 128];

        float m = -1e30f;
        #pragma unroll
        for (int i = 0; i < 8; i++)
            m = fmaxf(m, fmaxf(fmaxf(v[i].x, v[i].y), fmaxf(v[i].z, v[i].w)));
        #pragma unroll
        for (int o = 16; o; o >>= 1) m = fmaxf(m, __shfl_xor_sync(0xffffffffu, m, o));

        float ssum = 0.f;
        #pragma unroll
        for (int i = 0; i < 8; i++) {
            v[i].x = __expf(v[i].x - m); v[i].y = __expf(v[i].y - m);
            v[i].z = __expf(v[i].z - m); v[i].w = __expf(v[i].w - m);
            ssum += v[i].x + v[i].y + v[i].z + v[i].w;
        }
        #pragma unroll
        for (int o = 16; o; o >>= 1) ssum += __shfl_xor_sync(0xffffffffu, ssum, o);
        const float inv = 1.0f / ssum;

        float* srow = &S[(size_t)h * SMPAD];
        #pragma unroll
        for (int i = 0; i < 8; i++) {
            v[i].x *= inv; v[i].y *= inv; v[i].z *= inv; v[i].w *= inv;
            *(float4*)&row[lane * 4 + i * 128] = v[i];
            *(float4*)&srow[lane * 4 + i * 128] = v[i];
        }
    }
    __syncthreads();

    // head average: 256 threads x 4 columns
    const int c = tid * 4;
    float4 acc = make_float4(0.f, 0.f, 0.f, 0.f);
    #pragma unroll
    for (int h = 0; h < NH; h++) {
        float4 v = *(const float4*)&S[(size_t)h * SMPAD + c];
        acc.x += v.x; acc.y += v.y; acc.z += v.z; acc.w += v.w;
    }
    const float invh = 1.0f / NH;
    acc.x *= invh; acc.y *= invh; acc.z *= invh; acc.w *= invh;
    *(float4*)&avg[(((size_t)b * T_SEQ + t) * T_SEQ) + c] = acc;
}

// ============================================================
// attn[t, b, h*64+j] = sum_s p[bh,t,s] * v[s,b,h*64+j]
// 128(t) x 64(j) tile, BK=32, 8x4 microtile
// ============================================================
__global__ void __launch_bounds__(256)
pv_kernel() {
    __shared__ float Ps[32][132];   // [s][t]
    __shared__ float Vs[32][68];    // [s][j]
    const int bh = blockIdx.z;
    const int b = bh >> 4, h = bh & 15;
    const int t0 = blockIdx.x * 128;
    const int tid = threadIdx.x;
    const int tx = tid & 15, ty = tid >> 4;
    const size_t pbase = (size_t)bh * T_SEQ * T_SEQ;
    const size_t vbase = (size_t)b * E3 + 2 * EMB + h * HD;

    float acc[8][4] = {};
    for (int s0 = 0; s0 < T_SEQ; s0 += 32) {
        #pragma unroll
        for (int i = 0; i < 4; i++) {      // P tile: 128 t-rows x 32 s
            int f = tid + i * 256;
            int row = f >> 3;              // 0..127
            int c = (f & 7) * 4;           // 0..28
            float4 p4 = *(const float4*)&g_scores[pbase + (size_t)(t0 + row) * T_SEQ + s0 + c];
            Ps[c + 0][row] = p4.x; Ps[c + 1][row] = p4.y;
            Ps[c + 2][row] = p4.z; Ps[c + 3][row] = p4.w;
        }
        #pragma unroll
        for (int i = 0; i < 2; i++) {      // V tile: 32 s-rows x 64 j
            int f = tid + i * 256;
            int row = f >> 4;              // 0..31
            int c = (f & 15) * 4;          // 0..60
            float4 vv = *(const float4*)&g_qkv[(size_t)(s0 + row) * BSZ * E3 + vbase + c];
            *(float4*)&Vs[row][c] = vv;
        }
        __syncthreads();
        #pragma unroll
        for (int kk = 0; kk < 32; kk++) {
            float pr[8], vr[4];
            *(float4*)pr       = *(const float4*)&Ps[kk][ty * 8];
            *(float4*)(pr + 4) = *(const float4*)&Ps[kk][ty * 8 + 4];
            *(float4*)vr       = *(const float4*)&Vs[kk][tx * 4];
            #pragma unroll
            for (int i = 0; i < 8; i++)
                #pragma unroll
                for (int j = 0; j < 4; j++)
                    acc[i][j] += pr[i] * vr[j];
        }
        __syncthreads();
    }
    #pragma unroll
    for (int i = 0; i < 8; i++) {
        float4 o;
        o.x = acc[i][0]; o.y = acc[i][1]; o.z = acc[i][2]; o.w = acc[i][3];
        *(float4*)&g_attn[(size_t)(t0 + ty * 8 + i) * BSZ * EMB + (size_t)b * EMB + h * HD + tx * 4] = o;
    }
}

// ============================================================
extern "C" void kernel_launch(void* const* d_in, const int* in_sizes, int n_in,
                              void* d_out, int out_size) {
    const float* query = (const float*)d_in[0];
    const float* w_in  = (const float*)d_in[1];
    const float* b_in  = (const float*)d_in[2];
    const float* w_out = (const float*)d_in[3];
    const float* b_out = (const float*)d_in[4];
    const float* rpk   = (const float*)d_in[5];
    float* out = (float*)d_out;

    void *p_qkv_v, *p_attn_v;
    cudaGetSymbolAddress(&p_qkv_v, g_qkv);
    cudaGetSymbolAddress(&p_attn_v, g_attn);
    float* p_qkv = (float*)p_qkv_v;
    float* p_attn = (float*)p_attn_v;

    const int scores_smem = 2 * 64 * 132 * sizeof(float);    // 67584
    const int smax_smem = 16 * SMPAD * sizeof(float);        // 65792
    cudaFuncSetAttribute(scores_kernel, cudaFuncAttributeMaxDynamicSharedMemorySize, scores_smem);
    cudaFuncSetAttribute(softmax_avg_kernel, cudaFuncAttributeMaxDynamicSharedMemorySize, smax_smem);

    // 1. QKV projection: [8192,1024] @ [3072,1024]^T
    {
        dim3 grid(E3 / 128, (T_SEQ * BSZ) / 128);
        gemm128<<<grid, 256>>>(query, w_in, b_in, p_qkv, T_SEQ * BSZ, E3, EMB);
    }
    // 2. qrel table
    {
        dim3 grid(T_SEQ, BH);
        qrel_kernel<<<grid, 128>>>(rpk);
    }
    // 3. scores = scaled q·k + qrel lookup
    {
        dim3 grid(T_SEQ / 128, T_SEQ / 128, BH);
        scores_kernel<<<grid, 256, scores_smem>>>();
    }
    // 4. fused softmax (in place) + avg weights (second output)
    {
        dim3 grid(T_SEQ, BSZ);
        softmax_avg_kernel<<<grid, 256, smax_smem>>>(out + (size_t)T_SEQ * BSZ * EMB);
    }
    // 5. attn = p @ v
    {
        dim3 grid(T_SEQ / 128, 1, BH);
        pv_kernel<<<grid, 256>>>();
    }
    // 6. out projection -> first chunk of d_out
    {
        dim3 grid(EMB / 128, (T_SEQ * BSZ) / 128);
        gemm128<<<grid, 256>>>(p_attn, w_out, b_out, out, T_SEQ * BSZ, EMB, EMB);
    }
}

// round 4
// speedup vs baseline: 1.7059x; 1.3456x over previous
#include <cuda_runtime.h>
#include <cuda_bf16.h>
#include <cstdint>
#include <cstddef>

#define T_SEQ 1024
#define BSZ   8
#define EMB   1024
#define NH    16
#define HD    64
#define NR    33
#define E3    (3*EMB)
#define SCALE 0.125f
#define BH    (BSZ*NH)

// ---- scratch (static device globals; no allocations allowed) ----
__device__ float g_qkv[(size_t)T_SEQ * BSZ * E3];          // 96 MB  [T,B,3E]
__device__ float g_scores[(size_t)BH * T_SEQ * T_SEQ];     // 512 MB [BH,T,S]
__device__ float g_qrel[(size_t)BH * T_SEQ * NR];          // 16.5 MB
__device__ float g_attn[(size_t)T_SEQ * BSZ * EMB];        // 32 MB  [T,B,E]

// ============================================================
// Tensor-core split-bf16 GEMM: C[M,N] = A[M,K] @ W[N,K]^T + bias
// fp32 accuracy via 3-term bf16 split (AhBh + AhBl + AlBh).
// 128x128 tile, BK=32, 256 threads (8 warps, 2x4), warp tile 64x32,
// mma.sync.m16n8k16, double-buffered smem of pre-split bf16x2.
// Requires M%128==0, N%128==0, K%32==0.
// ============================================================
#define GT_BUF (128 * 17)        // uint32 per buffer per array

__device__ __forceinline__ uint32_t pack_bf(__nv_bfloat16 a, __nv_bfloat16 b) {
    return (uint32_t)__bfloat16_as_ushort(a) | ((uint32_t)__bfloat16_as_ushort(b) << 16);
}
__device__ __forceinline__ void split_pair(float x, float y, uint32_t& h, uint32_t& l) {
    __nv_bfloat16 hx = __float2bfloat16_rn(x), hy = __float2bfloat16_rn(y);
    h = pack_bf(hx, hy);
    __nv_bfloat16 lx = __float2bfloat16_rn(x - __bfloat162float(hx));
    __nv_bfloat16 ly = __float2bfloat16_rn(y - __bfloat162float(hy));
    l = pack_bf(lx, ly);
}

#define MMA16816(c, a, b)                                                     \
    asm volatile("mma.sync.aligned.m16n8k16.row.col.f32.bf16.bf16.f32 "       \
        "{%0,%1,%2,%3}, {%4,%5,%6,%7}, {%8,%9}, {%0,%1,%2,%3};"               \
        : "+f"((c)[0]), "+f"((c)[1]), "+f"((c)[2]), "+f"((c)[3])              \
        : "r"((a)[0]), "r"((a)[1]), "r"((a)[2]), "r"((a)[3]),                 \
          "r"((b)[0]), "r"((b)[1]));

__global__ void __launch_bounds__(256)
gemm_tc(const float* __restrict__ A, const float* __restrict__ W,
        const float* __restrict__ bias, float* __restrict__ C,
        int M, int N, int K) {
    extern __shared__ uint32_t sm[];
    uint32_t* Ah = sm;
    uint32_t* Al = sm + 2 * GT_BUF;
    uint32_t* Wh = sm + 4 * GT_BUF;
    uint32_t* Wl = sm + 6 * GT_BUF;

    const int tid  = threadIdx.x;
    const int warp = tid >> 5, lane = tid & 31;
    const int g = lane >> 2, t = lane & 3;
    const int m0 = (warp >> 2) * 64;      // 0 or 64
    const int n0 = (warp & 3) * 32;       // 0..96
    const int row0 = blockIdx.y * 128, col0 = blockIdx.x * 128;

    int frow[4], fcol[4];
    #pragma unroll
    for (int i = 0; i < 4; i++) {
        int f = tid + i * 256;
        frow[i] = f >> 3;           // 0..127
        fcol[i] = (f & 7) * 4;      // 0..28
    }

    float4 fa[4], fw[4];

#define GT_FETCH(k0)                                                           \
    _Pragma("unroll")                                                          \
    for (int i = 0; i < 4; i++) {                                              \
        fa[i] = *(const float4*)&A[(size_t)(row0 + frow[i]) * K + (k0) + fcol[i]]; \
        fw[i] = *(const float4*)&W[(size_t)(col0 + frow[i]) * K + (k0) + fcol[i]]; \
    }

#define GT_STORE(bf)                                                           \
    _Pragma("unroll")                                                          \
    for (int i = 0; i < 4; i++) {                                              \
        int base = (bf) * GT_BUF + frow[i] * 17 + (fcol[i] >> 1);              \
        uint32_t h0, l0, h1, l1;                                               \
        split_pair(fa[i].x, fa[i].y, h0, l0);                                  \
        split_pair(fa[i].z, fa[i].w, h1, l1);                                  \
        Ah[base] = h0; Ah[base + 1] = h1;                                      \
        Al[base] = l0; Al[base + 1] = l1;                                      \
        split_pair(fw[i].x, fw[i].y, h0, l0);                                  \
        split_pair(fw[i].z, fw[i].w, h1, l1);                                  \
        Wh[base] = h0; Wh[base + 1] = h1;                                      \
        Wl[base] = l0; Wl[base + 1] = l1;                                      \
    }

    float acc[4][4][4] = {};

#define GT_COMPUTE(bf)                                                         \
    _Pragma("unroll")                                                          \
    for (int ks = 0; ks < 2; ks++) {                                           \
        const int kc = ks * 8;                                                 \
        uint32_t bh[4][2], bl[4][2];                                           \
        _Pragma("unroll")                                                      \
        for (int ni = 0; ni < 4; ni++) {                                       \
            int idx = (bf) * GT_BUF + (n0 + ni * 8 + g) * 17 + kc + t;         \
            bh[ni][0] = Wh[idx]; bh[ni][1] = Wh[idx + 4];                      \
            bl[ni][0] = Wl[idx]; bl[ni][1] = Wl[idx + 4];                      \
        }                                                                      \
        _Pragma("unroll")                                                      \
        for (int mi = 0; mi < 4; mi++) {                                       \
            int i1 = (bf) * GT_BUF + (m0 + mi * 16 + g) * 17 + kc + t;         \
            int i2 = i1 + 8 * 17;                                              \
            uint32_t ah[4], al[4];                                             \
            ah[0] = Ah[i1]; ah[1] = Ah[i2]; ah[2] = Ah[i1 + 4]; ah[3] = Ah[i2 + 4]; \
            al[0] = Al[i1]; al[1] = Al[i2]; al[2] = Al[i1 + 4]; al[3] = Al[i2 + 4]; \
            _Pragma("unroll")                                                  \
            for (int ni = 0; ni < 4; ni++) {                                   \
                MMA16816(acc[mi][ni], ah, bh[ni])                              \
                MMA16816(acc[mi][ni], ah, bl[ni])                              \
                MMA16816(acc[mi][ni], al, bh[ni])                              \
            }                                                                  \
        }                                                                      \
    }

    GT_FETCH(0)
    GT_STORE(0)
    __syncthreads();
    int buf = 0;
    const int nk = K >> 5;
    for (int it = 1; it < nk; it++) {
        GT_FETCH(it * 32)
        GT_COMPUTE(buf)
        GT_STORE(buf ^ 1)
        __syncthreads();
        buf ^= 1;
    }
    GT_COMPUTE(buf)

    // epilogue
    #pragma unroll
    for (int mi = 0; mi < 4; mi++) {
        const int rA = row0 + m0 + mi * 16 + g;
        #pragma unroll
        for (int ni = 0; ni < 4; ni++) {
            const int cc = col0 + n0 + ni * 8 + 2 * t;
            const float b0 = bias[cc], b1 = bias[cc + 1];
            float2 o0 = { acc[mi][ni][0] + b0, acc[mi][ni][1] + b1 };
            float2 o1 = { acc[mi][ni][2] + b0, acc[mi][ni][3] + b1 };
            *(float2*)&C[(size_t)rA * N + cc] = o0;
            *(float2*)&C[(size_t)(rA + 8) * N + cc] = o1;
        }
    }
}

// ============================================================
// qrel[bh, t, r] = SCALE * sum_j q[t,b,h*64+j] * rpk[r, j]
// ============================================================
__global__ void __launch_bounds__(128)
qrel_kernel(const float* __restrict__ rpk) {
    const int t = blockIdx.x;
    const int bh = blockIdx.y;
    const int b = bh >> 4, h = bh & 15;
    __shared__ float qs[HD];
    __shared__ float rs[NR * HD];
    const int tid = threadIdx.x;
    if (tid < HD)
        qs[tid] = g_qkv[(size_t)t * BSZ * E3 + (size_t)b * E3 + h * HD + tid] * SCALE;
    for (int i = tid; i < NR * HD; i += 128) rs[i] = rpk[i];
    __syncthreads();
    if (tid < NR) {
        float s = 0.f;
        #pragma unroll
        for (int j = 0; j < HD; j++) s += qs[j] * rs[tid * HD + j];
        g_qrel[((size_t)bh * T_SEQ + t) * NR + tid] = s;
    }
}

// ============================================================
// scores[bh,t,s] = SCALE*q[t]·k[s] + qrel[bh,t,clip(s-t)+16]
// 128x128 tile over (t,s); K=64; 8x8 microtile; dynamic smem 67.6KB
// ============================================================
__global__ void __launch_bounds__(256)
scores_kernel() {
    extern __shared__ float dyn[];
    float (*Qs)[132] = (float(*)[132])dyn;               // [64][132]  [j][t]
    float (*Ks)[132] = (float(*)[132])(dyn + 64 * 132);  // [64][132]  [j][s]

    const int bh = blockIdx.z;
    const int b = bh >> 4, h = bh & 15;
    const int t0 = blockIdx.y * 128, s0 = blockIdx.x * 128;
    const int tid = threadIdx.x;
    const int tx = tid & 15, ty = tid >> 4;
    const size_t qoff = (size_t)b * E3 + h * HD;

    #pragma unroll
    for (int i = 0; i < 8; i++) {
        int f = tid + i * 256;
        int row = f >> 4;           // 0..127
        int c = (f & 15) * 4;       // 0..60
        float4 q = *(const float4*)&g_qkv[(size_t)(t0 + row) * BSZ * E3 + qoff + c];
        float4 k = *(const float4*)&g_qkv[(size_t)(s0 + row) * BSZ * E3 + qoff + EMB + c];
        Qs[c + 0][row] = q.x * SCALE; Qs[c + 1][row] = q.y * SCALE;
        Qs[c + 2][row] = q.z * SCALE; Qs[c + 3][row] = q.w * SCALE;
        Ks[c + 0][row] = k.x; Ks[c + 1][row] = k.y;
        Ks[c + 2][row] = k.z; Ks[c + 3][row] = k.w;
    }
    __syncthreads();

    float acc[8][8] = {};
    #pragma unroll 16
    for (int j = 0; j < 64; j++) {
        float qr[8], kr[8];
        *(float4*)qr       = *(const float4*)&Qs[j][ty * 8];
        *(float4*)(qr + 4) = *(const float4*)&Qs[j][ty * 8 + 4];
        *(float4*)kr       = *(const float4*)&Ks[j][tx * 8];
        *(float4*)(kr + 4) = *(const float4*)&Ks[j][tx * 8 + 4];
        #pragma unroll
        for (int i = 0; i < 8; i++)
            #pragma unroll
            for (int jj = 0; jj < 8; jj++)
                acc[i][jj] += qr[i] * kr[jj];
    }

    #pragma unroll
    for (int i = 0; i < 8; i++) {
        int t = t0 + ty * 8 + i;
        const float* qr_row = &g_qrel[((size_t)bh * T_SEQ + t) * NR];
        float* orow = &g_scores[((size_t)bh * T_SEQ + t) * T_SEQ];
        #pragma unroll
        for (int jj = 0; jj < 8; jj++) {
            int s = s0 + tx * 8 + jj;
            int d = s - t;
            d = d < -16 ? -16 : (d > 16 ? 16 : d);
            orow[s] = acc[i][jj] + qr_row[d + 16];
        }
    }
}

// ============================================================
// Fused softmax (in place) + head-averaged weights.
// One block per (t, b): 16 head-rows of length 1024.
// ============================================================
#define SMPAD 1028
__global__ void __launch_bounds__(256)
softmax_avg_kernel(float* __restrict__ avg) {
    extern __shared__ float S[];    // [16][SMPAD]
    const int t = blockIdx.x;
    const int b = blockIdx.y;
    const int tid = threadIdx.x;
    const int warp = tid >> 5, lane = tid & 31;

    #pragma unroll
    for (int rep = 0; rep < 2; rep++) {
        const int h = warp + rep * 8;
        float* row = g_scores + (((size_t)(b * NH + h)) * T_SEQ + t) * T_SEQ;
        float4 v[8];
        #pragma unroll
        for (int i = 0; i < 8; i++)
            v[i] = *(const float4*)&row[lane * 4 + i * 128];

        float m = -1e30f;
        #pragma unroll
        for (int i = 0; i < 8; i++)
            m = fmaxf(m, fmaxf(fmaxf(v[i].x, v[i].y), fmaxf(v[i].z, v[i].w)));
        #pragma unroll
        for (int o = 16; o; o >>= 1) m = fmaxf(m, __shfl_xor_sync(0xffffffffu, m, o));

        float ssum = 0.f;
        #pragma unroll
        for (int i = 0; i < 8; i++) {
            v[i].x = __expf(v[i].x - m); v[i].y = __expf(v[i].y - m);
            v[i].z = __expf(v[i].z - m); v[i].w = __expf(v[i].w - m);
            ssum += v[i].x + v[i].y + v[i].z + v[i].w;
        }
        #pragma unroll
        for (int o = 16; o; o >>= 1) ssum += __shfl_xor_sync(0xffffffffu, ssum, o);
        const float inv = 1.0f / ssum;

        float* srow = &S[(size_t)h * SMPAD];
        #pragma unroll
        for (int i = 0; i < 8; i++) {
            v[i].x *= inv; v[i].y *= inv; v[i].z *= inv; v[i].w *= inv;
            *(float4*)&row[lane * 4 + i * 128] = v[i];
            *(float4*)&srow[lane * 4 + i * 128] = v[i];
        }
    }
    __syncthreads();

    const int c = tid * 4;
    float4 acc = make_float4(0.f, 0.f, 0.f, 0.f);
    #pragma unroll
    for (int h = 0; h < NH; h++) {
        float4 v = *(const float4*)&S[(size_t)h * SMPAD + c];
        acc.x += v.x; acc.y += v.y; acc.z += v.z; acc.w += v.w;
    }
    const float invh = 1.0f / NH;
    acc.x *= invh; acc.y *= invh; acc.z *= invh; acc.w *= invh;
    *(float4*)&avg[(((size_t)b * T_SEQ + t) * T_SEQ) + c] = acc;
}

// ============================================================
// attn[t, b, h*64+j] = sum_s p[bh,t,s] * v[s,b,h*64+j]
// 128(t) x 64(j) tile, BK=32, 8x4 microtile
// ============================================================
__global__ void __launch_bounds__(256)
pv_kernel() {
    __shared__ float Ps[32][132];   // [s][t]
    __shared__ float Vs[32][68];    // [s][j]
    const int bh = blockIdx.z;
    const int b = bh >> 4, h = bh & 15;
    const int t0 = blockIdx.x * 128;
    const int tid = threadIdx.x;
    const int tx = tid & 15, ty = tid >> 4;
    const size_t pbase = (size_t)bh * T_SEQ * T_SEQ;
    const size_t vbase = (size_t)b * E3 + 2 * EMB + h * HD;

    float acc[8][4] = {};
    for (int s0 = 0; s0 < T_SEQ; s0 += 32) {
        #pragma unroll
        for (int i = 0; i < 4; i++) {
            int f = tid + i * 256;
            int row = f >> 3;
            int c = (f & 7) * 4;
            float4 p4 = *(const float4*)&g_scores[pbase + (size_t)(t0 + row) * T_SEQ + s0 + c];
            Ps[c + 0][row] = p4.x; Ps[c + 1][row] = p4.y;
            Ps[c + 2][row] = p4.z; Ps[c + 3][row] = p4.w;
        }
        #pragma unroll
        for (int i = 0; i < 2; i++) {
            int f = tid + i * 256;
            int row = f >> 4;
            int c = (f & 15) * 4;
            float4 vv = *(const float4*)&g_qkv[(size_t)(s0 + row) * BSZ * E3 + vbase + c];
            *(float4*)&Vs[row][c] = vv;
        }
        __syncthreads();
        #pragma unroll
        for (int kk = 0; kk < 32; kk++) {
            float pr[8], vr[4];
            *(float4*)pr       = *(const float4*)&Ps[kk][ty * 8];
            *(float4*)(pr + 4) = *(const float4*)&Ps[kk][ty * 8 + 4];
            *(float4*)vr       = *(const float4*)&Vs[kk][tx * 4];
            #pragma unroll
            for (int i = 0; i < 8; i++)
                #pragma unroll
                for (int j = 0; j < 4; j++)
                    acc[i][j] += pr[i] * vr[j];
        }
        __syncthreads();
    }
    #pragma unroll
    for (int i = 0; i < 8; i++) {
        float4 o;
        o.x = acc[i][0]; o.y = acc[i][1]; o.z = acc[i][2]; o.w = acc[i][3];
        *(float4*)&g_attn[(size_t)(t0 + ty * 8 + i) * BSZ * EMB + (size_t)b * EMB + h * HD + tx * 4] = o;
    }
}

// ============================================================
extern "C" void kernel_launch(void* const* d_in, const int* in_sizes, int n_in,
                              void* d_out, int out_size) {
    const float* query = (const float*)d_in[0];
    const float* w_in  = (const float*)d_in[1];
    const float* b_in  = (const float*)d_in[2];
    const float* w_out = (const float*)d_in[3];
    const float* b_out = (const float*)d_in[4];
    const float* rpk   = (const float*)d_in[5];
    float* out = (float*)d_out;

    void *p_qkv_v, *p_attn_v;
    cudaGetSymbolAddress(&p_qkv_v, g_qkv);
    cudaGetSymbolAddress(&p_attn_v, g_attn);
    float* p_qkv = (float*)p_qkv_v;
    float* p_attn = (float*)p_attn_v;

    const int gemm_smem   = 8 * GT_BUF * sizeof(uint32_t);   // 69632
    const int scores_smem = 2 * 64 * 132 * sizeof(float);    // 67584
    const int smax_smem   = 16 * SMPAD * sizeof(float);      // 65792
    cudaFuncSetAttribute(gemm_tc, cudaFuncAttributeMaxDynamicSharedMemorySize, gemm_smem);
    cudaFuncSetAttribute(scores_kernel, cudaFuncAttributeMaxDynamicSharedMemorySize, scores_smem);
    cudaFuncSetAttribute(softmax_avg_kernel, cudaFuncAttributeMaxDynamicSharedMemorySize, smax_smem);

    // 1. QKV projection: [8192,1024] @ [3072,1024]^T  (tensor cores)
    {
        dim3 grid(E3 / 128, (T_SEQ * BSZ) / 128);
        gemm_tc<<<grid, 256, gemm_smem>>>(query, w_in, b_in, p_qkv, T_SEQ * BSZ, E3, EMB);
    }
    // 2. qrel table
    {
        dim3 grid(T_SEQ, BH);
        qrel_kernel<<<grid, 128>>>(rpk);
    }
    // 3. scores = scaled q·k + qrel lookup
    {
        dim3 grid(T_SEQ / 128, T_SEQ / 128, BH);
        scores_kernel<<<grid, 256, scores_smem>>>();
    }
    // 4. fused softmax (in place) + avg weights (second output)
    {
        dim3 grid(T_SEQ, BSZ);
        softmax_avg_kernel<<<grid, 256, smax_smem>>>(out + (size_t)T_SEQ * BSZ * EMB);
    }
    // 5. attn = p @ v
    {
        dim3 grid(T_SEQ / 128, 1, BH);
        pv_kernel<<<grid, 256>>>();
    }
    // 6. out projection -> first chunk of d_out  (tensor cores)
    {
        dim3 grid(EMB / 128, (T_SEQ * BSZ) / 128);
        gemm_tc<<<grid, 256, gemm_smem>>>(p_attn, w_out, b_out, out, T_SEQ * BSZ, EMB, EMB);
    }
}

// round 7
// speedup vs baseline: 1.9674x; 1.1532x over previous
#include <cuda_runtime.h>
#include <cuda_bf16.h>
#include <cstdint>
#include <cstddef>

#define T_SEQ 1024
#define BSZ   8
#define EMB   1024
#define NH    16
#define HD    64
#define NR    33
#define E3    (3*EMB)
#define SCALE 0.125f
#define BH    (BSZ*NH)

// ---- scratch (static device globals; no allocations allowed) ----
__device__ float g_qkv[(size_t)T_SEQ * BSZ * E3];          // 96 MB  [T,B,3E]
__device__ float g_scores[(size_t)BH * T_SEQ * T_SEQ];     // 512 MB [BH,T,S]
__device__ float g_qrel[(size_t)BH * T_SEQ * NR];          // 16.5 MB
__device__ float g_attn[(size_t)T_SEQ * BSZ * EMB];        // 32 MB  [T,B,E]

// ============================================================
// split-bf16 helpers (3-term fp32-accurate emulation)
// ============================================================
__device__ __forceinline__ uint32_t pack_bf(__nv_bfloat16 a, __nv_bfloat16 b) {
    return (uint32_t)__bfloat16_as_ushort(a) | ((uint32_t)__bfloat16_as_ushort(b) << 16);
}
__device__ __forceinline__ void split_pair(float x, float y, uint32_t& h, uint32_t& l) {
    __nv_bfloat16 hx = __float2bfloat16_rn(x), hy = __float2bfloat16_rn(y);
    h = pack_bf(hx, hy);
    __nv_bfloat16 lx = __float2bfloat16_rn(x - __bfloat162float(hx));
    __nv_bfloat16 ly = __float2bfloat16_rn(y - __bfloat162float(hy));
    l = pack_bf(lx, ly);
}

#define MMA16816(c, a, b)                                                     \
    asm volatile("mma.sync.aligned.m16n8k16.row.col.f32.bf16.bf16.f32 "       \
        "{%0,%1,%2,%3}, {%4,%5,%6,%7}, {%8,%9}, {%0,%1,%2,%3};"               \
        : "+f"((c)[0]), "+f"((c)[1]), "+f"((c)[2]), "+f"((c)[3])              \
        : "r"((a)[0]), "r"((a)[1]), "r"((a)[2]), "r"((a)[3]),                 \
          "r"((b)[0]), "r"((b)[1]));

// ============================================================
// Tensor-core GEMM: C[M,N] = A[M,K] @ W[N,K]^T + bias
// 128x128 tile, BK=32, 8 warps (2x4), warp tile 64x32, double-buffered.
// ============================================================
#define GT_BUF (128 * 17)

__global__ void __launch_bounds__(256)
gemm_tc(const float* __restrict__ A, const float* __restrict__ W,
        const float* __restrict__ bias, float* __restrict__ C,
        int M, int N, int K) {
    extern __shared__ uint32_t sm[];
    uint32_t* Ah = sm;
    uint32_t* Al = sm + 2 * GT_BUF;
    uint32_t* Wh = sm + 4 * GT_BUF;
    uint32_t* Wl = sm + 6 * GT_BUF;

    const int tid  = threadIdx.x;
    const int warp = tid >> 5, lane = tid & 31;
    const int g = lane >> 2, t = lane & 3;
    const int m0 = (warp >> 2) * 64;
    const int n0 = (warp & 3) * 32;
    const int row0 = blockIdx.y * 128, col0 = blockIdx.x * 128;

    int frow[4], fcol[4];
    #pragma unroll
    for (int i = 0; i < 4; i++) {
        int f = tid + i * 256;
        frow[i] = f >> 3;
        fcol[i] = (f & 7) * 4;
    }

    float4 fa[4], fw[4];

#define GT_FETCH(k0)                                                           \
    _Pragma("unroll")                                                          \
    for (int i = 0; i < 4; i++) {                                              \
        fa[i] = *(const float4*)&A[(size_t)(row0 + frow[i]) * K + (k0) + fcol[i]]; \
        fw[i] = *(const float4*)&W[(size_t)(col0 + frow[i]) * K + (k0) + fcol[i]]; \
    }

#define GT_STORE(bf)                                                           \
    _Pragma("unroll")                                                          \
    for (int i = 0; i < 4; i++) {                                              \
        int base = (bf) * GT_BUF + frow[i] * 17 + (fcol[i] >> 1);              \
        uint32_t h0, l0, h1, l1;                                               \
        split_pair(fa[i].x, fa[i].y, h0, l0);                                  \
        split_pair(fa[i].z, fa[i].w, h1, l1);                                  \
        Ah[base] = h0; Ah[base + 1] = h1;                                      \
        Al[base] = l0; Al[base + 1] = l1;                                      \
        split_pair(fw[i].x, fw[i].y, h0, l0);                                  \
        split_pair(fw[i].z, fw[i].w, h1, l1);                                  \
        Wh[base] = h0; Wh[base + 1] = h1;                                      \
        Wl[base] = l0; Wl[base + 1] = l1;                                      \
    }

    float acc[4][4][4] = {};

#define GT_COMPUTE(bf)                                                         \
    _Pragma("unroll")                                                          \
    for (int ks = 0; ks < 2; ks++) {                                           \
        const int kc = ks * 8;                                                 \
        uint32_t bhf[4][2], blf[4][2];                                         \
        _Pragma("unroll")                                                      \
        for (int ni = 0; ni < 4; ni++) {                                       \
            int idx = (bf) * GT_BUF + (n0 + ni * 8 + g) * 17 + kc + t;         \
            bhf[ni][0] = Wh[idx]; bhf[ni][1] = Wh[idx + 4];                    \
            blf[ni][0] = Wl[idx]; blf[ni][1] = Wl[idx + 4];                    \
        }                                                                      \
        _Pragma("unroll")                                                      \
        for (int mi = 0; mi < 4; mi++) {                                       \
            int i1 = (bf) * GT_BUF + (m0 + mi * 16 + g) * 17 + kc + t;         \
            int i2 = i1 + 8 * 17;                                              \
            uint32_t ah[4], al[4];                                             \
            ah[0] = Ah[i1]; ah[1] = Ah[i2]; ah[2] = Ah[i1 + 4]; ah[3] = Ah[i2 + 4]; \
            al[0] = Al[i1]; al[1] = Al[i2]; al[2] = Al[i1 + 4]; al[3] = Al[i2 + 4]; \
            _Pragma("unroll")                                                  \
            for (int ni = 0; ni < 4; ni++) {                                   \
                MMA16816(acc[mi][ni], ah, bhf[ni])                             \
                MMA16816(acc[mi][ni], ah, blf[ni])                             \
                MMA16816(acc[mi][ni], al, bhf[ni])                             \
            }                                                                  \
        }                                                                      \
    }

    GT_FETCH(0)
    GT_STORE(0)
    __syncthreads();
    int buf = 0;
    const int nk = K >> 5;
    for (int it = 1; it < nk; it++) {
        GT_FETCH(it * 32)
        GT_COMPUTE(buf)
        GT_STORE(buf ^ 1)
        __syncthreads();
        buf ^= 1;
    }
    GT_COMPUTE(buf)

    #pragma unroll
    for (int mi = 0; mi < 4; mi++) {
        const int rA = row0 + m0 + mi * 16 + g;
        #pragma unroll
        for (int ni = 0; ni < 4; ni++) {
            const int cc = col0 + n0 + ni * 8 + 2 * t;
            const float b0 = bias[cc], b1 = bias[cc + 1];
            float2 o0 = { acc[mi][ni][0] + b0, acc[mi][ni][1] + b1 };
            float2 o1 = { acc[mi][ni][2] + b0, acc[mi][ni][3] + b1 };
            *(float2*)&C[(size_t)rA * N + cc] = o0;
            *(float2*)&C[(size_t)(rA + 8) * N + cc] = o1;
        }
    }
}

// ============================================================
// qrel[bh, t, r] = SCALE * sum_j q[t,b,h*64+j] * rpk[r, j]
// ============================================================
__global__ void __launch_bounds__(128)
qrel_kernel(const float* __restrict__ rpk) {
    const int t = blockIdx.x;
    const int bh = blockIdx.y;
    const int b = bh >> 4, h = bh & 15;
    __shared__ float qs[HD];
    __shared__ float rs[NR * HD];
    const int tid = threadIdx.x;
    if (tid < HD)
        qs[tid] = g_qkv[(size_t)t * BSZ * E3 + (size_t)b * E3 + h * HD + tid] * SCALE;
    for (int i = tid; i < NR * HD; i += 128) rs[i] = rpk[i];
    __syncthreads();
    if (tid < NR) {
        float s = 0.f;
        #pragma unroll
        for (int j = 0; j < HD; j++) s += qs[j] * rs[tid * HD + j];
        g_qrel[((size_t)bh * T_SEQ + t) * NR + tid] = s;
    }
}

// ============================================================
// scores_tc: scores[bh,t,s] = (SCALE*q)·k + qrel lookup
// 128x128 tile, K=64 single-stage, 8 warps (2x4), warp tile 64x32.
// smem: 4 arrays of 128x33 u32 = 67.6 KB
// ============================================================
#define SC_ROW 33
#define SC_BUF (128 * SC_ROW)

__global__ void __launch_bounds__(256)
scores_tc() {
    extern __shared__ uint32_t sm[];
    uint32_t* Qh = sm;
    uint32_t* Ql = sm + SC_BUF;
    uint32_t* Kh = sm + 2 * SC_BUF;
    uint32_t* Kl = sm + 3 * SC_BUF;

    const int bh = blockIdx.z;
    const int b = bh >> 4, h = bh & 15;
    const int t0 = blockIdx.y * 128, s0 = blockIdx.x * 128;
    const int tid = threadIdx.x;
    const int warp = tid >> 5, lane = tid & 31;
    const int g = lane >> 2, t = lane & 3;
    const int m0 = (warp >> 2) * 64;
    const int n0 = (warp & 3) * 32;
    const size_t qoff = (size_t)b * E3 + h * HD;

    #pragma unroll
    for (int i = 0; i < 8; i++) {
        int f = tid + i * 256;
        int row = f >> 4;          // 0..127
        int c = (f & 15) * 4;      // 0..60
        float4 q = *(const float4*)&g_qkv[(size_t)(t0 + row) * BSZ * E3 + qoff + c];
        float4 k = *(const float4*)&g_qkv[(size_t)(s0 + row) * BSZ * E3 + qoff + EMB + c];
        int base = row * SC_ROW + (c >> 1);
        uint32_t h0, l0, h1, l1;
        split_pair(q.x * SCALE, q.y * SCALE, h0, l0);
        split_pair(q.z * SCALE, q.w * SCALE, h1, l1);
        Qh[base] = h0; Qh[base + 1] = h1;
        Ql[base] = l0; Ql[base + 1] = l1;
        split_pair(k.x, k.y, h0, l0);
        split_pair(k.z, k.w, h1, l1);
        Kh[base] = h0; Kh[base + 1] = h1;
        Kl[base] = l0; Kl[base + 1] = l1;
    }
    __syncthreads();

    float acc[4][4][4] = {};
    #pragma unroll
    for (int kc = 0; kc < 32; kc += 8) {
        uint32_t bhf[4][2], blf[4][2];
        #pragma unroll
        for (int ni = 0; ni < 4; ni++) {
            int idx = (n0 + ni * 8 + g) * SC_ROW + kc + t;
            bhf[ni][0] = Kh[idx]; bhf[ni][1] = Kh[idx + 4];
            blf[ni][0] = Kl[idx]; blf[ni][1] = Kl[idx + 4];
        }
        #pragma unroll
        for (int mi = 0; mi < 4; mi++) {
            int i1 = (m0 + mi * 16 + g) * SC_ROW + kc + t;
            int i2 = i1 + 8 * SC_ROW;
            uint32_t ah[4], al[4];
            ah[0] = Qh[i1]; ah[1] = Qh[i2]; ah[2] = Qh[i1 + 4]; ah[3] = Qh[i2 + 4];
            al[0] = Ql[i1]; al[1] = Ql[i2]; al[2] = Ql[i1 + 4]; al[3] = Ql[i2 + 4];
            #pragma unroll
            for (int ni = 0; ni < 4; ni++) {
                MMA16816(acc[mi][ni], ah, bhf[ni])
                MMA16816(acc[mi][ni], ah, blf[ni])
                MMA16816(acc[mi][ni], al, bhf[ni])
            }
        }
    }

    // epilogue: add relative-position term, write fp32 scores
    #pragma unroll
    for (int mi = 0; mi < 4; mi++) {
        #pragma unroll
        for (int rr = 0; rr < 2; rr++) {
            const int tI = t0 + m0 + mi * 16 + g + rr * 8;
            const float* qr_row = &g_qrel[((size_t)bh * T_SEQ + tI) * NR];
            float* orow = &g_scores[((size_t)bh * T_SEQ + tI) * T_SEQ];
            #pragma unroll
            for (int ni = 0; ni < 4; ni++) {
                const int sI = s0 + n0 + ni * 8 + 2 * t;
                int d0 = sI - tI;     d0 = d0 < -16 ? -16 : (d0 > 16 ? 16 : d0);
                int d1 = sI + 1 - tI; d1 = d1 < -16 ? -16 : (d1 > 16 ? 16 : d1);
                float2 o;
                o.x = acc[mi][ni][rr * 2 + 0] + qr_row[d0 + 16];
                o.y = acc[mi][ni][rr * 2 + 1] + qr_row[d1 + 16];
                *(float2*)&orow[sI] = o;
            }
        }
    }
}

// ============================================================
// Fused softmax (in place) + head-averaged weights.
// ============================================================
#define SMPAD 1028
__global__ void __launch_bounds__(256)
softmax_avg_kernel(float* __restrict__ avg) {
    extern __shared__ float S[];
    const int t = blockIdx.x;
    const int b = blockIdx.y;
    const int tid = threadIdx.x;
    const int warp = tid >> 5, lane = tid & 31;

    #pragma unroll
    for (int rep = 0; rep < 2; rep++) {
        const int h = warp + rep * 8;
        float* row = g_scores + (((size_t)(b * NH + h)) * T_SEQ + t) * T_SEQ;
        float4 v[8];
        #pragma unroll
        for (int i = 0; i < 8; i++)
            v[i] = *(const float4*)&row[lane * 4 + i * 128];

        float m = -1e30f;
        #pragma unroll
        for (int i = 0; i < 8; i++)
            m = fmaxf(m, fmaxf(fmaxf(v[i].x, v[i].y), fmaxf(v[i].z, v[i].w)));
        #pragma unroll
        for (int o = 16; o; o >>= 1) m = fmaxf(m, __shfl_xor_sync(0xffffffffu, m, o));

        float ssum = 0.f;
        #pragma unroll
        for (int i = 0; i < 8; i++) {
            v[i].x = __expf(v[i].x - m); v[i].y = __expf(v[i].y - m);
            v[i].z = __expf(v[i].z - m); v[i].w = __expf(v[i].w - m);
            ssum += v[i].x + v[i].y + v[i].z + v[i].w;
        }
        #pragma unroll
        for (int o = 16; o; o >>= 1) ssum += __shfl_xor_sync(0xffffffffu, ssum, o);
        const float inv = 1.0f / ssum;

        float* srow = &S[(size_t)h * SMPAD];
        #pragma unroll
        for (int i = 0; i < 8; i++) {
            v[i].x *= inv; v[i].y *= inv; v[i].z *= inv; v[i].w *= inv;
            *(float4*)&row[lane * 4 + i * 128] = v[i];
            *(float4*)&srow[lane * 4 + i * 128] = v[i];
        }
    }
    __syncthreads();

    const int c = tid * 4;
    float4 acc = make_float4(0.f, 0.f, 0.f, 0.f);
    #pragma unroll
    for (int h = 0; h < NH; h++) {
        float4 v = *(const float4*)&S[(size_t)h * SMPAD + c];
        acc.x += v.x; acc.y += v.y; acc.z += v.z; acc.w += v.w;
    }
    const float invh = 1.0f / NH;
    acc.x *= invh; acc.y *= invh; acc.z *= invh; acc.w *= invh;
    *(float4*)&avg[(((size_t)b * T_SEQ + t) * T_SEQ) + c] = acc;
}

// ============================================================
// attn[t, b, h*64+j] = sum_s p[bh,t,s] * v[s,b,h*64+j]
// 128(t) x 64(j) tile, BK=32, 8x4 microtile  (SIMT, R4-proven)
// ============================================================
__global__ void __launch_bounds__(256)
pv_kernel() {
    __shared__ float Ps[32][132];   // [s][t]
    __shared__ float Vs[32][68];    // [s][j]
    const int bh = blockIdx.z;
    const int b = bh >> 4, h = bh & 15;
    const int t0 = blockIdx.x * 128;
    const int tid = threadIdx.x;
    const int tx = tid & 15, ty = tid >> 4;
    const size_t pbase = (size_t)bh * T_SEQ * T_SEQ;
    const size_t vbase = (size_t)b * E3 + 2 * EMB + h * HD;

    float acc[8][4] = {};
    for (int s0 = 0; s0 < T_SEQ; s0 += 32) {
        #pragma unroll
        for (int i = 0; i < 4; i++) {
            int f = tid + i * 256;
            int row = f >> 3;
            int c = (f & 7) * 4;
            float4 p4 = *(const float4*)&g_scores[pbase + (size_t)(t0 + row) * T_SEQ + s0 + c];
            Ps[c + 0][row] = p4.x; Ps[c + 1][row] = p4.y;
            Ps[c + 2][row] = p4.z; Ps[c + 3][row] = p4.w;
        }
        #pragma unroll
        for (int i = 0; i < 2; i++) {
            int f = tid + i * 256;
            int row = f >> 4;
            int c = (f & 15) * 4;
            float4 vv = *(const float4*)&g_qkv[(size_t)(s0 + row) * BSZ * E3 + vbase + c];
            *(float4*)&Vs[row][c] = vv;
        }
        __syncthreads();
        #pragma unroll
        for (int kk = 0; kk < 32; kk++) {
            float pr[8], vr[4];
            *(float4*)pr       = *(const float4*)&Ps[kk][ty * 8];
            *(float4*)(pr + 4) = *(const float4*)&Ps[kk][ty * 8 + 4];
            *(float4*)vr       = *(const float4*)&Vs[kk][tx * 4];
            #pragma unroll
            for (int i = 0; i < 8; i++)
                #pragma unroll
                for (int j = 0; j < 4; j++)
                    acc[i][j] += pr[i] * vr[j];
        }
        __syncthreads();
    }
    #pragma unroll
    for (int i = 0; i < 8; i++) {
        float4 o;
        o.x = acc[i][0]; o.y = acc[i][1]; o.z = acc[i][2]; o.w = acc[i][3];
        *(float4*)&g_attn[(size_t)(t0 + ty * 8 + i) * BSZ * EMB + (size_t)b * EMB + h * HD + tx * 4] = o;
    }
}

// ============================================================
extern "C" void kernel_launch(void* const* d_in, const int* in_sizes, int n_in,
                              void* d_out, int out_size) {
    const float* query = (const float*)d_in[0];
    const float* w_in  = (const float*)d_in[1];
    const float* b_in  = (const float*)d_in[2];
    const float* w_out = (const float*)d_in[3];
    const float* b_out = (const float*)d_in[4];
    const float* rpk   = (const float*)d_in[5];
    float* out = (float*)d_out;

    void *p_qkv_v, *p_attn_v;
    cudaGetSymbolAddress(&p_qkv_v, g_qkv);
    cudaGetSymbolAddress(&p_attn_v, g_attn);
    float* p_qkv = (float*)p_qkv_v;
    float* p_attn = (float*)p_attn_v;

    const int gemm_smem   = 8 * GT_BUF * sizeof(uint32_t);    // 69632
    const int scores_smem = 4 * SC_BUF * sizeof(uint32_t);    // 67584
    const int smax_smem   = 16 * SMPAD * sizeof(float);       // 65792
    cudaFuncSetAttribute(gemm_tc, cudaFuncAttributeMaxDynamicSharedMemorySize, gemm_smem);
    cudaFuncSetAttribute(scores_tc, cudaFuncAttributeMaxDynamicSharedMemorySize, scores_smem);
    cudaFuncSetAttribute(softmax_avg_kernel, cudaFuncAttributeMaxDynamicSharedMemorySize, smax_smem);

    // 1. QKV projection (tensor cores)
    {
        dim3 grid(E3 / 128, (T_SEQ * BSZ) / 128);
        gemm_tc<<<grid, 256, gemm_smem>>>(query, w_in, b_in, p_qkv, T_SEQ * BSZ, E3, EMB);
    }
    // 2. qrel table
    {
        dim3 grid(T_SEQ, BH);
        qrel_kernel<<<grid, 128>>>(rpk);
    }
    // 3. scores (tensor cores, fused qrel epilogue)
    {
        dim3 grid(T_SEQ / 128, T_SEQ / 128, BH);
        scores_tc<<<grid, 256, scores_smem>>>();
    }
    // 4. fused softmax (in place) + avg weights
    {
        dim3 grid(T_SEQ, BSZ);
        softmax_avg_kernel<<<grid, 256, smax_smem>>>(out + (size_t)T_SEQ * BSZ * EMB);
    }
    // 5. attn = p @ v (SIMT, R4-proven)
    {
        dim3 grid(T_SEQ / 128, 1, BH);
        pv_kernel<<<grid, 256>>>();
    }
    // 6. out projection (tensor cores)
    {
        dim3 grid(EMB / 128, (T_SEQ * BSZ) / 128);
        gemm_tc<<<grid, 256, gemm_smem>>>(p_attn, w_out, b_out, out, T_SEQ * BSZ, EMB, EMB);
    }
}

// round 8
// speedup vs baseline: 2.0174x; 1.0254x over previous
#include <cuda_runtime.h>
#include <cuda_bf16.h>
#include <cstdint>
#include <cstddef>

#define T_SEQ 1024
#define BSZ   8
#define EMB   1024
#define NH    16
#define HD    64
#define NR    33
#define E3    (3*EMB)
#define SCALE 0.125f
#define BH    (BSZ*NH)

// ---- scratch (static device globals; no allocations allowed) ----
__device__ float g_qkv[(size_t)T_SEQ * BSZ * E3];          // 96 MB  [T,B,3E]
__device__ float g_scores[(size_t)BH * T_SEQ * T_SEQ];     // 512 MB [BH,T,S]
__device__ float g_qrel[(size_t)BH * T_SEQ * NR];          // 16.5 MB
__device__ float g_attn[(size_t)T_SEQ * BSZ * EMB];        // 32 MB  [T,B,E]

// ============================================================
// split-bf16 helpers (3-term fp32-accurate emulation)
// ============================================================
__device__ __forceinline__ uint32_t pack_bf(__nv_bfloat16 a, __nv_bfloat16 b) {
    return (uint32_t)__bfloat16_as_ushort(a) | ((uint32_t)__bfloat16_as_ushort(b) << 16);
}
__device__ __forceinline__ void split_pair(float x, float y, uint32_t& h, uint32_t& l) {
    __nv_bfloat16 hx = __float2bfloat16_rn(x), hy = __float2bfloat16_rn(y);
    h = pack_bf(hx, hy);
    __nv_bfloat16 lx = __float2bfloat16_rn(x - __bfloat162float(hx));
    __nv_bfloat16 ly = __float2bfloat16_rn(y - __bfloat162float(hy));
    l = pack_bf(lx, ly);
}

#define MMA16816(c, a, b)                                                     \
    asm volatile("mma.sync.aligned.m16n8k16.row.col.f32.bf16.bf16.f32 "       \
        "{%0,%1,%2,%3}, {%4,%5,%6,%7}, {%8,%9}, {%0,%1,%2,%3};"               \
        : "+f"((c)[0]), "+f"((c)[1]), "+f"((c)[2]), "+f"((c)[3])              \
        : "r"((a)[0]), "r"((a)[1]), "r"((a)[2]), "r"((a)[3]),                 \
          "r"((b)[0]), "r"((b)[1]));

// ============================================================
// Tensor-core GEMM: C[M,N] = A[M,K] @ W[N,K]^T + bias
// 128x128 tile, BK=32, 8 warps (2x4), warp tile 64x32, double-buffered.
// ============================================================
#define GT_BUF (128 * 17)

__global__ void __launch_bounds__(256)
gemm_tc(const float* __restrict__ A, const float* __restrict__ W,
        const float* __restrict__ bias, float* __restrict__ C,
        int M, int N, int K) {
    extern __shared__ uint32_t sm[];
    uint32_t* Ah = sm;
    uint32_t* Al = sm + 2 * GT_BUF;
    uint32_t* Wh = sm + 4 * GT_BUF;
    uint32_t* Wl = sm + 6 * GT_BUF;

    const int tid  = threadIdx.x;
    const int warp = tid >> 5, lane = tid & 31;
    const int g = lane >> 2, t = lane & 3;
    const int m0 = (warp >> 2) * 64;
    const int n0 = (warp & 3) * 32;
    const int row0 = blockIdx.y * 128, col0 = blockIdx.x * 128;

    int frow[4], fcol[4];
    #pragma unroll
    for (int i = 0; i < 4; i++) {
        int f = tid + i * 256;
        frow[i] = f >> 3;
        fcol[i] = (f & 7) * 4;
    }

    float4 fa[4], fw[4];

#define GT_FETCH(k0)                                                           \
    _Pragma("unroll")                                                          \
    for (int i = 0; i < 4; i++) {                                              \
        fa[i] = *(const float4*)&A[(size_t)(row0 + frow[i]) * K + (k0) + fcol[i]]; \
        fw[i] = *(const float4*)&W[(size_t)(col0 + frow[i]) * K + (k0) + fcol[i]]; \
    }

#define GT_STORE(bf)                                                           \
    _Pragma("unroll")                                                          \
    for (int i = 0; i < 4; i++) {                                              \
        int base = (bf) * GT_BUF + frow[i] * 17 + (fcol[i] >> 1);              \
        uint32_t h0, l0, h1, l1;                                               \
        split_pair(fa[i].x, fa[i].y, h0, l0);                                  \
        split_pair(fa[i].z, fa[i].w, h1, l1);                                  \
        Ah[base] = h0; Ah[base + 1] = h1;                                      \
        Al[base] = l0; Al[base + 1] = l1;                                      \
        split_pair(fw[i].x, fw[i].y, h0, l0);                                  \
        split_pair(fw[i].z, fw[i].w, h1, l1);                                  \
        Wh[base] = h0; Wh[base + 1] = h1;                                      \
        Wl[base] = l0; Wl[base + 1] = l1;                                      \
    }

    float acc[4][4][4] = {};

#define GT_COMPUTE(bf)                                                         \
    _Pragma("unroll")                                                          \
    for (int ks = 0; ks < 2; ks++) {                                           \
        const int kc = ks * 8;                                                 \
        uint32_t bhf[4][2], blf[4][2];                                         \
        _Pragma("unroll")                                                      \
        for (int ni = 0; ni < 4; ni++) {                                       \
            int idx = (bf) * GT_BUF + (n0 + ni * 8 + g) * 17 + kc + t;         \
            bhf[ni][0] = Wh[idx]; bhf[ni][1] = Wh[idx + 4];                    \
            blf[ni][0] = Wl[idx]; blf[ni][1] = Wl[idx + 4];                    \
        }                                                                      \
        _Pragma("unroll")                                                      \
        for (int mi = 0; mi < 4; mi++) {                                       \
            int i1 = (bf) * GT_BUF + (m0 + mi * 16 + g) * 17 + kc + t;         \
            int i2 = i1 + 8 * 17;                                              \
            uint32_t ah[4], al[4];                                             \
            ah[0] = Ah[i1]; ah[1] = Ah[i2]; ah[2] = Ah[i1 + 4]; ah[3] = Ah[i2 + 4]; \
            al[0] = Al[i1]; al[1] = Al[i2]; al[2] = Al[i1 + 4]; al[3] = Al[i2 + 4]; \
            _Pragma("unroll")                                                  \
            for (int ni = 0; ni < 4; ni++) {                                   \
                MMA16816(acc[mi][ni], ah, bhf[ni])                             \
                MMA16816(acc[mi][ni], ah, blf[ni])                             \
                MMA16816(acc[mi][ni], al, bhf[ni])                             \
            }                                                                  \
        }                                                                      \
    }

    GT_FETCH(0)
    GT_STORE(0)
    __syncthreads();
    int buf = 0;
    const int nk = K >> 5;
    for (int it = 1; it < nk; it++) {
        GT_FETCH(it * 32)
        GT_COMPUTE(buf)
        GT_STORE(buf ^ 1)
        __syncthreads();
        buf ^= 1;
    }
    GT_COMPUTE(buf)

    #pragma unroll
    for (int mi = 0; mi < 4; mi++) {
        const int rA = row0 + m0 + mi * 16 + g;
        #pragma unroll
        for (int ni = 0; ni < 4; ni++) {
            const int cc = col0 + n0 + ni * 8 + 2 * t;
            const float b0 = bias[cc], b1 = bias[cc + 1];
            float2 o0 = { acc[mi][ni][0] + b0, acc[mi][ni][1] + b1 };
            float2 o1 = { acc[mi][ni][2] + b0, acc[mi][ni][3] + b1 };
            *(float2*)&C[(size_t)rA * N + cc] = o0;
            *(float2*)&C[(size_t)(rA + 8) * N + cc] = o1;
        }
    }
}

// ============================================================
// qrel[bh, t, r] = SCALE * sum_j q[t,b,h*64+j] * rpk[r, j]
// ============================================================
__global__ void __launch_bounds__(128)
qrel_kernel(const float* __restrict__ rpk) {
    const int t = blockIdx.x;
    const int bh = blockIdx.y;
    const int b = bh >> 4, h = bh & 15;
    __shared__ float qs[HD];
    __shared__ float rs[NR * HD];
    const int tid = threadIdx.x;
    if (tid < HD)
        qs[tid] = g_qkv[(size_t)t * BSZ * E3 + (size_t)b * E3 + h * HD + tid] * SCALE;
    for (int i = tid; i < NR * HD; i += 128) rs[i] = rpk[i];
    __syncthreads();
    if (tid < NR) {
        float s = 0.f;
        #pragma unroll
        for (int j = 0; j < HD; j++) s += qs[j] * rs[tid * HD + j];
        g_qrel[((size_t)bh * T_SEQ + t) * NR + tid] = s;
    }
}

// ============================================================
// scores_tc: scores[bh,t,s] = (SCALE*q)·k + qrel lookup
// 128x128 tile, K=64 single-stage, 8 warps (2x4), warp tile 64x32.
// ============================================================
#define SC_ROW 33
#define SC_BUF (128 * SC_ROW)

__global__ void __launch_bounds__(256)
scores_tc() {
    extern __shared__ uint32_t sm[];
    uint32_t* Qh = sm;
    uint32_t* Ql = sm + SC_BUF;
    uint32_t* Kh = sm + 2 * SC_BUF;
    uint32_t* Kl = sm + 3 * SC_BUF;

    const int bh = blockIdx.z;
    const int b = bh >> 4, h = bh & 15;
    const int t0 = blockIdx.y * 128, s0 = blockIdx.x * 128;
    const int tid = threadIdx.x;
    const int warp = tid >> 5, lane = tid & 31;
    const int g = lane >> 2, t = lane & 3;
    const int m0 = (warp >> 2) * 64;
    const int n0 = (warp & 3) * 32;
    const size_t qoff = (size_t)b * E3 + h * HD;

    #pragma unroll
    for (int i = 0; i < 8; i++) {
        int f = tid + i * 256;
        int row = f >> 4;          // 0..127
        int c = (f & 15) * 4;      // 0..60
        float4 q = *(const float4*)&g_qkv[(size_t)(t0 + row) * BSZ * E3 + qoff + c];
        float4 k = *(const float4*)&g_qkv[(size_t)(s0 + row) * BSZ * E3 + qoff + EMB + c];
        int base = row * SC_ROW + (c >> 1);
        uint32_t h0, l0, h1, l1;
        split_pair(q.x * SCALE, q.y * SCALE, h0, l0);
        split_pair(q.z * SCALE, q.w * SCALE, h1, l1);
        Qh[base] = h0; Qh[base + 1] = h1;
        Ql[base] = l0; Ql[base + 1] = l1;
        split_pair(k.x, k.y, h0, l0);
        split_pair(k.z, k.w, h1, l1);
        Kh[base] = h0; Kh[base + 1] = h1;
        Kl[base] = l0; Kl[base + 1] = l1;
    }
    __syncthreads();

    float acc[4][4][4] = {};
    #pragma unroll
    for (int kc = 0; kc < 32; kc += 8) {
        uint32_t bhf[4][2], blf[4][2];
        #pragma unroll
        for (int ni = 0; ni < 4; ni++) {
            int idx = (n0 + ni * 8 + g) * SC_ROW + kc + t;
            bhf[ni][0] = Kh[idx]; bhf[ni][1] = Kh[idx + 4];
            blf[ni][0] = Kl[idx]; blf[ni][1] = Kl[idx + 4];
        }
        #pragma unroll
        for (int mi = 0; mi < 4; mi++) {
            int i1 = (m0 + mi * 16 + g) * SC_ROW + kc + t;
            int i2 = i1 + 8 * SC_ROW;
            uint32_t ah[4], al[4];
            ah[0] = Qh[i1]; ah[1] = Qh[i2]; ah[2] = Qh[i1 + 4]; ah[3] = Qh[i2 + 4];
            al[0] = Ql[i1]; al[1] = Ql[i2]; al[2] = Ql[i1 + 4]; al[3] = Ql[i2 + 4];
            #pragma unroll
            for (int ni = 0; ni < 4; ni++) {
                MMA16816(acc[mi][ni], ah, bhf[ni])
                MMA16816(acc[mi][ni], ah, blf[ni])
                MMA16816(acc[mi][ni], al, bhf[ni])
            }
        }
    }

    #pragma unroll
    for (int mi = 0; mi < 4; mi++) {
        #pragma unroll
        for (int rr = 0; rr < 2; rr++) {
            const int tI = t0 + m0 + mi * 16 + g + rr * 8;
            const float* qr_row = &g_qrel[((size_t)bh * T_SEQ + tI) * NR];
            float* orow = &g_scores[((size_t)bh * T_SEQ + tI) * T_SEQ];
            #pragma unroll
            for (int ni = 0; ni < 4; ni++) {
                const int sI = s0 + n0 + ni * 8 + 2 * t;
                int d0 = sI - tI;     d0 = d0 < -16 ? -16 : (d0 > 16 ? 16 : d0);
                int d1 = sI + 1 - tI; d1 = d1 < -16 ? -16 : (d1 > 16 ? 16 : d1);
                float2 o;
                o.x = acc[mi][ni][rr * 2 + 0] + qr_row[d0 + 16];
                o.y = acc[mi][ni][rr * 2 + 1] + qr_row[d1 + 16];
                *(float2*)&orow[sI] = o;
            }
        }
    }
}

// ============================================================
// Fused softmax (in place) + head-averaged weights.
// ============================================================
#define SMPAD 1028
__global__ void __launch_bounds__(256)
softmax_avg_kernel(float* __restrict__ avg) {
    extern __shared__ float S[];
    const int t = blockIdx.x;
    const int b = blockIdx.y;
    const int tid = threadIdx.x;
    const int warp = tid >> 5, lane = tid & 31;

    #pragma unroll
    for (int rep = 0; rep < 2; rep++) {
        const int h = warp + rep * 8;
        float* row = g_scores + (((size_t)(b * NH + h)) * T_SEQ + t) * T_SEQ;
        float4 v[8];
        #pragma unroll
        for (int i = 0; i < 8; i++)
            v[i] = *(const float4*)&row[lane * 4 + i * 128];

        float m = -1e30f;
        #pragma unroll
        for (int i = 0; i < 8; i++)
            m = fmaxf(m, fmaxf(fmaxf(v[i].x, v[i].y), fmaxf(v[i].z, v[i].w)));
        #pragma unroll
        for (int o = 16; o; o >>= 1) m = fmaxf(m, __shfl_xor_sync(0xffffffffu, m, o));

        float ssum = 0.f;
        #pragma unroll
        for (int i = 0; i < 8; i++) {
            v[i].x = __expf(v[i].x - m); v[i].y = __expf(v[i].y - m);
            v[i].z = __expf(v[i].z - m); v[i].w = __expf(v[i].w - m);
            ssum += v[i].x + v[i].y + v[i].z + v[i].w;
        }
        #pragma unroll
        for (int o = 16; o; o >>= 1) ssum += __shfl_xor_sync(0xffffffffu, ssum, o);
        const float inv = 1.0f / ssum;

        float* srow = &S[(size_t)h * SMPAD];
        #pragma unroll
        for (int i = 0; i < 8; i++) {
            v[i].x *= inv; v[i].y *= inv; v[i].z *= inv; v[i].w *= inv;
            *(float4*)&row[lane * 4 + i * 128] = v[i];
            *(float4*)&srow[lane * 4 + i * 128] = v[i];
        }
    }
    __syncthreads();

    const int c = tid * 4;
    float4 acc = make_float4(0.f, 0.f, 0.f, 0.f);
    #pragma unroll
    for (int h = 0; h < NH; h++) {
        float4 v = *(const float4*)&S[(size_t)h * SMPAD + c];
        acc.x += v.x; acc.y += v.y; acc.z += v.z; acc.w += v.w;
    }
    const float invh = 1.0f / NH;
    acc.x *= invh; acc.y *= invh; acc.z *= invh; acc.w *= invh;
    *(float4*)&avg[(((size_t)b * T_SEQ + t) * T_SEQ) + c] = acc;
}

// ============================================================
// pv_tc: attn[t,b,h*64+j] = sum_s p[bh,t,s] * v[s,b,h*64+j]
// 128(t) x 64(j) tile, BK=32 double-buffered, 8 warps (4x2),
// warp tile 32x32. V transposed to [j][s-pair] during convert.
// ============================================================
#define PV_PB (128 * 17)
#define PV_VB (64 * 17)

__global__ void __launch_bounds__(256)
pv_tc() {
    extern __shared__ uint32_t sm[];
    uint32_t* Ph = sm;
    uint32_t* Pl = sm + 2 * PV_PB;
    uint32_t* Vh = sm + 4 * PV_PB;
    uint32_t* Vl = sm + 4 * PV_PB + 2 * PV_VB;

    const int bh = blockIdx.z;
    const int b = bh >> 4, h = bh & 15;
    const int t0 = blockIdx.x * 128;
    const int tid = threadIdx.x;
    const int warp = tid >> 5, lane = tid & 31;
    const int g = lane >> 2, t = lane & 3;
    const int m0 = (warp >> 1) * 32;     // 0,32,64,96
    const int n0 = (warp & 1) * 32;      // 0,32
    const size_t pbase = (size_t)bh * T_SEQ * T_SEQ;
    const size_t vbase = (size_t)b * E3 + 2 * EMB + h * HD;

    int frow[4], fcol[4];
    #pragma unroll
    for (int i = 0; i < 4; i++) {
        int f = tid + i * 256;
        frow[i] = f >> 3;           // 0..127
        fcol[i] = (f & 7) * 4;      // 0..28
    }
    const int sp = tid >> 4;        // 0..15 (s-pair)
    const int j4 = (tid & 15) * 4;  // 0..60

    float4 fp[4], va, vb;

#define PV_FETCH(s0v)                                                          \
    _Pragma("unroll")                                                          \
    for (int i = 0; i < 4; i++)                                                \
        fp[i] = *(const float4*)&g_scores[pbase + (size_t)(t0 + frow[i]) * T_SEQ + (s0v) + fcol[i]]; \
    va = *(const float4*)&g_qkv[(size_t)((s0v) + 2 * sp) * BSZ * E3 + vbase + j4];     \
    vb = *(const float4*)&g_qkv[(size_t)((s0v) + 2 * sp + 1) * BSZ * E3 + vbase + j4];

#define PV_STORE(bf)                                                           \
    _Pragma("unroll")                                                          \
    for (int i = 0; i < 4; i++) {                                              \
        int base = (bf) * PV_PB + frow[i] * 17 + (fcol[i] >> 1);               \
        uint32_t h0, l0, h1, l1;                                               \
        split_pair(fp[i].x, fp[i].y, h0, l0);                                  \
        split_pair(fp[i].z, fp[i].w, h1, l1);                                  \
        Ph[base] = h0; Ph[base + 1] = h1;                                      \
        Pl[base] = l0; Pl[base + 1] = l1;                                      \
    }                                                                          \
    {                                                                          \
        const float* pa = &va.x; const float* pb = &vb.x;                      \
        _Pragma("unroll")                                                      \
        for (int jj = 0; jj < 4; jj++) {                                       \
            uint32_t hh, ll;                                                   \
            split_pair(pa[jj], pb[jj], hh, ll);                                \
            Vh[(bf) * PV_VB + (j4 + jj) * 17 + sp] = hh;                       \
            Vl[(bf) * PV_VB + (j4 + jj) * 17 + sp] = ll;                       \
        }                                                                      \
    }

    float acc[2][4][4] = {};

#define PV_COMPUTE(bf)                                                         \
    _Pragma("unroll")                                                          \
    for (int ks = 0; ks < 2; ks++) {                                           \
        const int kc = ks * 8;                                                 \
        uint32_t bhf[4][2], blf[4][2];                                         \
        _Pragma("unroll")                                                      \
        for (int ni = 0; ni < 4; ni++) {                                       \
            int idx = (bf) * PV_VB + (n0 + ni * 8 + g) * 17 + kc + t;          \
            bhf[ni][0] = Vh[idx]; bhf[ni][1] = Vh[idx + 4];                    \
            blf[ni][0] = Vl[idx]; blf[ni][1] = Vl[idx + 4];                    \
        }                                                                      \
        _Pragma("unroll")                                                      \
        for (int mi = 0; mi < 2; mi++) {                                       \
            int i1 = (bf) * PV_PB + (m0 + mi * 16 + g) * 17 + kc + t;          \
            int i2 = i1 + 8 * 17;                                              \
            uint32_t ah[4], al[4];                                             \
            ah[0] = Ph[i1]; ah[1] = Ph[i2]; ah[2] = Ph[i1 + 4]; ah[3] = Ph[i2 + 4]; \
            al[0] = Pl[i1]; al[1] = Pl[i2]; al[2] = Pl[i1 + 4]; al[3] = Pl[i2 + 4]; \
            _Pragma("unroll")                                                  \
            for (int ni = 0; ni < 4; ni++) {                                   \
                MMA16816(acc[mi][ni], ah, bhf[ni])                             \
                MMA16816(acc[mi][ni], ah, blf[ni])                             \
                MMA16816(acc[mi][ni], al, bhf[ni])                             \
            }                                                                  \
        }                                                                      \
    }

    PV_FETCH(0)
    PV_STORE(0)
    __syncthreads();
    int buf = 0;
    for (int it = 1; it < 32; it++) {
        PV_FETCH(it * 32)
        PV_COMPUTE(buf)
        PV_STORE(buf ^ 1)
        __syncthreads();
        buf ^= 1;
    }
    PV_COMPUTE(buf)

    #pragma unroll
    for (int mi = 0; mi < 2; mi++) {
        const int rA = t0 + m0 + mi * 16 + g;
        #pragma unroll
        for (int ni = 0; ni < 4; ni++) {
            const int cc = n0 + ni * 8 + 2 * t;
            float2 o0 = { acc[mi][ni][0], acc[mi][ni][1] };
            float2 o1 = { acc[mi][ni][2], acc[mi][ni][3] };
            *(float2*)&g_attn[(size_t)rA * BSZ * EMB + (size_t)b * EMB + h * HD + cc] = o0;
            *(float2*)&g_attn[(size_t)(rA + 8) * BSZ * EMB + (size_t)b * EMB + h * HD + cc] = o1;
        }
    }
}

// ============================================================
extern "C" void kernel_launch(void* const* d_in, const int* in_sizes, int n_in,
                              void* d_out, int out_size) {
    const float* query = (const float*)d_in[0];
    const float* w_in  = (const float*)d_in[1];
    const float* b_in  = (const float*)d_in[2];
    const float* w_out = (const float*)d_in[3];
    const float* b_out = (const float*)d_in[4];
    const float* rpk   = (const float*)d_in[5];
    float* out = (float*)d_out;

    void *p_qkv_v, *p_attn_v;
    cudaGetSymbolAddress(&p_qkv_v, g_qkv);
    cudaGetSymbolAddress(&p_attn_v, g_attn);
    float* p_qkv = (float*)p_qkv_v;
    float* p_attn = (float*)p_attn_v;

    const int gemm_smem   = 8 * GT_BUF * sizeof(uint32_t);    // 69632
    const int scores_smem = 4 * SC_BUF * sizeof(uint32_t);    // 67584
    const int smax_smem   = 16 * SMPAD * sizeof(float);       // 65792
    const int pv_smem     = (4 * PV_PB + 4 * PV_VB) * sizeof(uint32_t);  // 52224
    cudaFuncSetAttribute(gemm_tc, cudaFuncAttributeMaxDynamicSharedMemorySize, gemm_smem);
    cudaFuncSetAttribute(scores_tc, cudaFuncAttributeMaxDynamicSharedMemorySize, scores_smem);
    cudaFuncSetAttribute(softmax_avg_kernel, cudaFuncAttributeMaxDynamicSharedMemorySize, smax_smem);
    cudaFuncSetAttribute(pv_tc, cudaFuncAttributeMaxDynamicSharedMemorySize, pv_smem);

    // 1. QKV projection (tensor cores)
    {
        dim3 grid(E3 / 128, (T_SEQ * BSZ) / 128);
        gemm_tc<<<grid, 256, gemm_smem>>>(query, w_in, b_in, p_qkv, T_SEQ * BSZ, E3, EMB);
    }
    // 2. qrel table
    {
        dim3 grid(T_SEQ, BH);
        qrel_kernel<<<grid, 128>>>(rpk);
    }
    // 3. scores (tensor cores, fused qrel epilogue)
    {
        dim3 grid(T_SEQ / 128, T_SEQ / 128, BH);
        scores_tc<<<grid, 256, scores_smem>>>();
    }
    // 4. fused softmax (in place) + avg weights
    {
        dim3 grid(T_SEQ, BSZ);
        softmax_avg_kernel<<<grid, 256, smax_smem>>>(out + (size_t)T_SEQ * BSZ * EMB);
    }
    // 5. attn = p @ v (tensor cores)
    {
        dim3 grid(T_SEQ / 128, 1, BH);
        pv_tc<<<grid, 256, pv_smem>>>();
    }
    // 6. out projection (tensor cores)
    {
        dim3 grid(EMB / 128, (T_SEQ * BSZ) / 128);
        gemm_tc<<<grid, 256, gemm_smem>>>(p_attn, w_out, b_out, out, T_SEQ * BSZ, EMB, EMB);
    }
}

// round 9
// speedup vs baseline: 2.0869x; 1.0344x over previous
#include <cuda_runtime.h>
#include <cuda_bf16.h>
#include <cstdint>
#include <cstddef>

#define T_SEQ 1024
#define BSZ   8
#define EMB   1024
#define NH    16
#define HD    64
#define NR    33
#define E3    (3*EMB)
#define SCALE 0.125f
#define BH    (BSZ*NH)

// ---- scratch (static device globals; no allocations allowed) ----
__device__ float g_qkv[(size_t)T_SEQ * BSZ * E3];          // 96 MB  [T,B,3E]
__device__ float g_scores[(size_t)BH * T_SEQ * T_SEQ];     // 512 MB [BH,T,S]
__device__ float g_qrel[(size_t)BH * T_SEQ * NR];          // 16.5 MB
// pre-split operand buffers (packed bf16x2 hi/lo)
__device__ uint32_t g_qh[(size_t)8192 * 512];              // query  [8192][K/2]
__device__ uint32_t g_ql[(size_t)8192 * 512];
__device__ uint32_t g_wih[(size_t)3072 * 512];             // w_in   [3072][K/2]
__device__ uint32_t g_wil[(size_t)3072 * 512];
__device__ uint32_t g_woh[(size_t)1024 * 512];             // w_out  [1024][K/2]
__device__ uint32_t g_wol[(size_t)1024 * 512];
__device__ uint32_t g_ath[(size_t)8192 * 512];             // attn   [t*B+b][E/2]
__device__ uint32_t g_atl[(size_t)8192 * 512];
__device__ uint32_t g_vth[(size_t)BH * 64 * 512];          // V^T    [bh][j][s/2]
__device__ uint32_t g_vtl[(size_t)BH * 64 * 512];
__device__ uint32_t g_ph[(size_t)BH * T_SEQ * 512];        // P      [bh][t][s/2]  256MB
__device__ uint32_t g_pl[(size_t)BH * T_SEQ * 512];

// ============================================================
__device__ __forceinline__ uint32_t pack_bf(__nv_bfloat16 a, __nv_bfloat16 b) {
    return (uint32_t)__bfloat16_as_ushort(a) | ((uint32_t)__bfloat16_as_ushort(b) << 16);
}
__device__ __forceinline__ void split_pair(float x, float y, uint32_t& h, uint32_t& l) {
    __nv_bfloat16 hx = __float2bfloat16_rn(x), hy = __float2bfloat16_rn(y);
    h = pack_bf(hx, hy);
    __nv_bfloat16 lx = __float2bfloat16_rn(x - __bfloat162float(hx));
    __nv_bfloat16 ly = __float2bfloat16_rn(y - __bfloat162float(hy));
    l = pack_bf(lx, ly);
}

#define MMA16816(c, a, b)                                                     \
    asm volatile("mma.sync.aligned.m16n8k16.row.col.f32.bf16.bf16.f32 "       \
        "{%0,%1,%2,%3}, {%4,%5,%6,%7}, {%8,%9}, {%0,%1,%2,%3};"               \
        : "+f"((c)[0]), "+f"((c)[1]), "+f"((c)[2]), "+f"((c)[3])              \
        : "r"((a)[0]), "r"((a)[1]), "r"((a)[2]), "r"((a)[3]),                 \
          "r"((b)[0]), "r"((b)[1]));

// ============================================================
// split_lin: fp32 src -> packed bf16x2 hi/lo (pairs along last dim)
// ============================================================
__global__ void __launch_bounds__(256)
split_lin(const float* __restrict__ src, uint32_t* __restrict__ dh,
          uint32_t* __restrict__ dl) {
    size_t i = (size_t)blockIdx.x * 256 + threadIdx.x;   // one float4 = 2 pairs
    float4 v = ((const float4*)src)[i];
    uint32_t h0, l0, h1, l1;
    split_pair(v.x, v.y, h0, l0);
    split_pair(v.z, v.w, h1, l1);
    uint2 ho = {h0, h1}, lo = {l0, l1};
    ((uint2*)dh)[i] = ho;
    ((uint2*)dl)[i] = lo;
}

// ============================================================
// vt_split: V (in g_qkv) -> transposed split  [bh][j][s-pair]
// block: (s-chunk of 64, bh); smem transpose
// ============================================================
__global__ void __launch_bounds__(256)
vt_split() {
    __shared__ float tile[64][68];
    const int s0 = blockIdx.x * 64;
    const int bh = blockIdx.y;
    const int b = bh >> 4, h = bh & 15;
    const size_t vbase = (size_t)b * E3 + 2 * EMB + h * HD;
    const int tid = threadIdx.x;

    #pragma unroll
    for (int i = 0; i < 4; i++) {
        int f = tid + i * 256;
        int row = f >> 4;            // 0..63 (s local)
        int col = (f & 15) * 4;      // 0..60 (j)
        float4 v = *(const float4*)&g_qkv[(size_t)(s0 + row) * BSZ * E3 + vbase + col];
        *(float4*)&tile[row][col] = v;
    }
    __syncthreads();

    const int j = tid >> 2;          // 0..63
    const int spq = (tid & 3) * 8;   // 8 s-pairs each
    const size_t obase = ((size_t)bh * 64 + j) * 512 + (s0 >> 1);
    #pragma unroll
    for (int q = 0; q < 8; q++) {
        int sl = 2 * (spq + q);
        uint32_t hh, ll;
        split_pair(tile[sl][j], tile[sl + 1][j], hh, ll);
        g_vth[obase + spq + q] = hh;
        g_vtl[obase + spq + q] = ll;
    }
}

// ============================================================
// gemm_tc2: C[M,N] = A@W^T + bias from PRE-SPLIT operands.
// 128x128 tile, BK=32, 8 warps (2x4), warp tile 64x32, double-buffered.
// smem row stride 20 u32 (uint4-aligned, conflict-free fragment loads).
// ============================================================
#define GT_ROW 20
#define GT_BUF (128 * GT_ROW)

__global__ void __launch_bounds__(256)
gemm_tc2(const uint32_t* __restrict__ Ahg, const uint32_t* __restrict__ Alg,
         const uint32_t* __restrict__ Whg, const uint32_t* __restrict__ Wlg,
         const float* __restrict__ bias, float* __restrict__ C,
         int M, int N, int K) {
    extern __shared__ uint32_t sm[];
    uint32_t* Ah = sm;
    uint32_t* Al = sm + 2 * GT_BUF;
    uint32_t* Wh = sm + 4 * GT_BUF;
    uint32_t* Wl = sm + 6 * GT_BUF;

    const int tid  = threadIdx.x;
    const int warp = tid >> 5, lane = tid & 31;
    const int g = lane >> 2, t = lane & 3;
    const int m0 = (warp >> 2) * 64;
    const int n0 = (warp & 3) * 32;
    const int row0 = blockIdx.y * 128, col0 = blockIdx.x * 128;
    const int K2 = K >> 1;

    int frow[2], fcol[2];
    #pragma unroll
    for (int i = 0; i < 2; i++) {
        int f = tid + i * 256;
        frow[i] = f >> 2;            // 0..127
        fcol[i] = (f & 3) * 4;       // 0,4,8,12 (u32 col)
    }

    uint4 pah[2], pal[2], pwh[2], pwl[2];

#define G2_FETCH(k0)                                                           \
    _Pragma("unroll")                                                          \
    for (int i = 0; i < 2; i++) {                                              \
        size_t ar = (size_t)(row0 + frow[i]) * K2 + ((k0) >> 1) + fcol[i];     \
        size_t wr = (size_t)(col0 + frow[i]) * K2 + ((k0) >> 1) + fcol[i];     \
        pah[i] = *(const uint4*)&Ahg[ar];                                      \
        pal[i] = *(const uint4*)&Alg[ar];                                      \
        pwh[i] = *(const uint4*)&Whg[wr];                                      \
        pwl[i] = *(const uint4*)&Wlg[wr];                                      \
    }

#define G2_STORE(bf)                                                           \
    _Pragma("unroll")                                                          \
    for (int i = 0; i < 2; i++) {                                              \
        int base = (bf) * GT_BUF + frow[i] * GT_ROW + fcol[i];                 \
        *(uint4*)&Ah[base] = pah[i];                                           \
        *(uint4*)&Al[base] = pal[i];                                           \
        *(uint4*)&Wh[base] = pwh[i];                                           \
        *(uint4*)&Wl[base] = pwl[i];                                           \
    }

    float acc[4][4][4] = {};

#define G2_COMPUTE(bf)                                                         \
    _Pragma("unroll")                                                          \
    for (int ks = 0; ks < 2; ks++) {                                           \
        const int kc = ks * 8;                                                 \
        uint32_t bhf[4][2], blf[4][2];                                         \
        _Pragma("unroll")                                                      \
        for (int ni = 0; ni < 4; ni++) {                                       \
            int idx = (bf) * GT_BUF + (n0 + ni * 8 + g) * GT_ROW + kc + t;     \
            bhf[ni][0] = Wh[idx]; bhf[ni][1] = Wh[idx + 4];                    \
            blf[ni][0] = Wl[idx]; blf[ni][1] = Wl[idx + 4];                    \
        }                                                                      \
        _Pragma("unroll")                                                      \
        for (int mi = 0; mi < 4; mi++) {                                       \
            int i1 = (bf) * GT_BUF + (m0 + mi * 16 + g) * GT_ROW + kc + t;     \
            int i2 = i1 + 8 * GT_ROW;                                          \
            uint32_t ah[4], al[4];                                             \
            ah[0] = Ah[i1]; ah[1] = Ah[i2]; ah[2] = Ah[i1 + 4]; ah[3] = Ah[i2 + 4]; \
            al[0] = Al[i1]; al[1] = Al[i2]; al[2] = Al[i1 + 4]; al[3] = Al[i2 + 4]; \
            _Pragma("unroll")                                                  \
            for (int ni = 0; ni < 4; ni++) {                                   \
                MMA16816(acc[mi][ni], ah, bhf[ni])                             \
                MMA16816(acc[mi][ni], ah, blf[ni])                             \
                MMA16816(acc[mi][ni], al, bhf[ni])                             \
            }                                                                  \
        }                                                                      \
    }

    G2_FETCH(0)
    G2_STORE(0)
    __syncthreads();
    int buf = 0;
    const int nk = K >> 5;
    for (int it = 1; it < nk; it++) {
        G2_FETCH(it * 32)
        G2_COMPUTE(buf)
        G2_STORE(buf ^ 1)
        __syncthreads();
        buf ^= 1;
    }
    G2_COMPUTE(buf)

    #pragma unroll
    for (int mi = 0; mi < 4; mi++) {
        const int rA = row0 + m0 + mi * 16 + g;
        #pragma unroll
        for (int ni = 0; ni < 4; ni++) {
            const int cc = col0 + n0 + ni * 8 + 2 * t;
            const float b0 = bias[cc], b1 = bias[cc + 1];
            float2 o0 = { acc[mi][ni][0] + b0, acc[mi][ni][1] + b1 };
            float2 o1 = { acc[mi][ni][2] + b0, acc[mi][ni][3] + b1 };
            *(float2*)&C[(size_t)rA * N + cc] = o0;
            *(float2*)&C[(size_t)(rA + 8) * N + cc] = o1;
        }
    }
}

// ============================================================
// qrel[bh, t, r] = SCALE * sum_j q[t,b,h*64+j] * rpk[r, j]
// ============================================================
__global__ void __launch_bounds__(128)
qrel_kernel(const float* __restrict__ rpk) {
    const int t = blockIdx.x;
    const int bh = blockIdx.y;
    const int b = bh >> 4, h = bh & 15;
    __shared__ float qs[HD];
    __shared__ float rs[NR * HD];
    const int tid = threadIdx.x;
    if (tid < HD)
        qs[tid] = g_qkv[(size_t)t * BSZ * E3 + (size_t)b * E3 + h * HD + tid] * SCALE;
    for (int i = tid; i < NR * HD; i += 128) rs[i] = rpk[i];
    __syncthreads();
    if (tid < NR) {
        float s = 0.f;
        #pragma unroll
        for (int j = 0; j < HD; j++) s += qs[j] * rs[tid * HD + j];
        g_qrel[((size_t)bh * T_SEQ + t) * NR + tid] = s;
    }
}

// ============================================================
// scores_tc: scores[bh,t,s] = (SCALE*q)·k + qrel lookup  (R7-proven)
// ============================================================
#define SC_ROW 33
#define SC_BUF (128 * SC_ROW)

__global__ void __launch_bounds__(256)
scores_tc() {
    extern __shared__ uint32_t sm[];
    uint32_t* Qh = sm;
    uint32_t* Ql = sm + SC_BUF;
    uint32_t* Kh = sm + 2 * SC_BUF;
    uint32_t* Kl = sm + 3 * SC_BUF;

    const int bh = blockIdx.z;
    const int b = bh >> 4, h = bh & 15;
    const int t0 = blockIdx.y * 128, s0 = blockIdx.x * 128;
    const int tid = threadIdx.x;
    const int warp = tid >> 5, lane = tid & 31;
    const int g = lane >> 2, t = lane & 3;
    const int m0 = (warp >> 2) * 64;
    const int n0 = (warp & 3) * 32;
    const size_t qoff = (size_t)b * E3 + h * HD;

    #pragma unroll
    for (int i = 0; i < 8; i++) {
        int f = tid + i * 256;
        int row = f >> 4;
        int c = (f & 15) * 4;
        float4 q = *(const float4*)&g_qkv[(size_t)(t0 + row) * BSZ * E3 + qoff + c];
        float4 k = *(const float4*)&g_qkv[(size_t)(s0 + row) * BSZ * E3 + qoff + EMB + c];
        int base = row * SC_ROW + (c >> 1);
        uint32_t h0, l0, h1, l1;
        split_pair(q.x * SCALE, q.y * SCALE, h0, l0);
        split_pair(q.z * SCALE, q.w * SCALE, h1, l1);
        Qh[base] = h0; Qh[base + 1] = h1;
        Ql[base] = l0; Ql[base + 1] = l1;
        split_pair(k.x, k.y, h0, l0);
        split_pair(k.z, k.w, h1, l1);
        Kh[base] = h0; Kh[base + 1] = h1;
        Kl[base] = l0; Kl[base + 1] = l1;
    }
    __syncthreads();

    float acc[4][4][4] = {};
    #pragma unroll
    for (int kc = 0; kc < 32; kc += 8) {
        uint32_t bhf[4][2], blf[4][2];
        #pragma unroll
        for (int ni = 0; ni < 4; ni++) {
            int idx = (n0 + ni * 8 + g) * SC_ROW + kc + t;
            bhf[ni][0] = Kh[idx]; bhf[ni][1] = Kh[idx + 4];
            blf[ni][0] = Kl[idx]; blf[ni][1] = Kl[idx + 4];
        }
        #pragma unroll
        for (int mi = 0; mi < 4; mi++) {
            int i1 = (m0 + mi * 16 + g) * SC_ROW + kc + t;
            int i2 = i1 + 8 * SC_ROW;
            uint32_t ah[4], al[4];
            ah[0] = Qh[i1]; ah[1] = Qh[i2]; ah[2] = Qh[i1 + 4]; ah[3] = Qh[i2 + 4];
            al[0] = Ql[i1]; al[1] = Ql[i2]; al[2] = Ql[i1 + 4]; al[3] = Ql[i2 + 4];
            #pragma unroll
            for (int ni = 0; ni < 4; ni++) {
                MMA16816(acc[mi][ni], ah, bhf[ni])
                MMA16816(acc[mi][ni], ah, blf[ni])
                MMA16816(acc[mi][ni], al, bhf[ni])
            }
        }
    }

    #pragma unroll
    for (int mi = 0; mi < 4; mi++) {
        #pragma unroll
        for (int rr = 0; rr < 2; rr++) {
            const int tI = t0 + m0 + mi * 16 + g + rr * 8;
            const float* qr_row = &g_qrel[((size_t)bh * T_SEQ + tI) * NR];
            float* orow = &g_scores[((size_t)bh * T_SEQ + tI) * T_SEQ];
            #pragma unroll
            for (int ni = 0; ni < 4; ni++) {
                const int sI = s0 + n0 + ni * 8 + 2 * t;
                int d0 = sI - tI;     d0 = d0 < -16 ? -16 : (d0 > 16 ? 16 : d0);
                int d1 = sI + 1 - tI; d1 = d1 < -16 ? -16 : (d1 > 16 ? 16 : d1);
                float2 o;
                o.x = acc[mi][ni][rr * 2 + 0] + qr_row[d0 + 16];
                o.y = acc[mi][ni][rr * 2 + 1] + qr_row[d1 + 16];
                *(float2*)&orow[sI] = o;
            }
        }
    }
}

// ============================================================
// Fused softmax + avg; writes P as SPLIT bf16x2 hi/lo (no fp32 P).
// ============================================================
#define SMPAD 1028
__global__ void __launch_bounds__(256)
softmax_avg_kernel(float* __restrict__ avg) {
    extern __shared__ float S[];
    const int t = blockIdx.x;
    const int b = blockIdx.y;
    const int tid = threadIdx.x;
    const int warp = tid >> 5, lane = tid & 31;

    #pragma unroll
    for (int rep = 0; rep < 2; rep++) {
        const int h = warp + rep * 8;
        const size_t prow = ((size_t)(b * NH + h)) * T_SEQ + t;
        const float* row = g_scores + prow * T_SEQ;
        float4 v[8];
        #pragma unroll
        for (int i = 0; i < 8; i++)
            v[i] = *(const float4*)&row[lane * 4 + i * 128];

        float m = -1e30f;
        #pragma unroll
        for (int i = 0; i < 8; i++)
            m = fmaxf(m, fmaxf(fmaxf(v[i].x, v[i].y), fmaxf(v[i].z, v[i].w)));
        #pragma unroll
        for (int o = 16; o; o >>= 1) m = fmaxf(m, __shfl_xor_sync(0xffffffffu, m, o));

        float ssum = 0.f;
        #pragma unroll
        for (int i = 0; i < 8; i++) {
            v[i].x = __expf(v[i].x - m); v[i].y = __expf(v[i].y - m);
            v[i].z = __expf(v[i].z - m); v[i].w = __expf(v[i].w - m);
            ssum += v[i].x + v[i].y + v[i].z + v[i].w;
        }
        #pragma unroll
        for (int o = 16; o; o >>= 1) ssum += __shfl_xor_sync(0xffffffffu, ssum, o);
        const float inv = 1.0f / ssum;

        float* srow = &S[(size_t)h * SMPAD];
        uint32_t* ph = g_ph + prow * 512;
        uint32_t* pl = g_pl + prow * 512;
        #pragma unroll
        for (int i = 0; i < 8; i++) {
            v[i].x *= inv; v[i].y *= inv; v[i].z *= inv; v[i].w *= inv;
            *(float4*)&srow[lane * 4 + i * 128] = v[i];
            uint32_t h0, l0, h1, l1;
            split_pair(v[i].x, v[i].y, h0, l0);
            split_pair(v[i].z, v[i].w, h1, l1);
            uint2 ho = {h0, h1}, lo = {l0, l1};
            *(uint2*)&ph[lane * 2 + i * 64] = ho;
            *(uint2*)&pl[lane * 2 + i * 64] = lo;
        }
    }
    __syncthreads();

    const int c = tid * 4;
    float4 acc = make_float4(0.f, 0.f, 0.f, 0.f);
    #pragma unroll
    for (int h = 0; h < NH; h++) {
        float4 v = *(const float4*)&S[(size_t)h * SMPAD + c];
        acc.x += v.x; acc.y += v.y; acc.z += v.z; acc.w += v.w;
    }
    const float invh = 1.0f / NH;
    acc.x *= invh; acc.y *= invh; acc.z *= invh; acc.w *= invh;
    *(float4*)&avg[(((size_t)b * T_SEQ + t) * T_SEQ) + c] = acc;
}

// ============================================================
// pv_tc2: attn = P @ V from pre-split P and transposed split V.
// Inner loop is pure uint4 copies + MMA. Epilogue writes split attn.
// ============================================================
#define PV_ROW 20
#define PV_PB (128 * PV_ROW)
#define PV_VB (64 * PV_ROW)

__global__ void __launch_bounds__(256)
pv_tc2() {
    extern __shared__ uint32_t sm[];
    uint32_t* Ph = sm;
    uint32_t* Pl = sm + 2 * PV_PB;
    uint32_t* Vh = sm + 4 * PV_PB;
    uint32_t* Vl = sm + 4 * PV_PB + 2 * PV_VB;

    const int bh = blockIdx.z;
    const int b = bh >> 4, h = bh & 15;
    const int t0 = blockIdx.x * 128;
    const int tid = threadIdx.x;
    const int warp = tid >> 5, lane = tid & 31;
    const int g = lane >> 2, t = lane & 3;
    const int m0 = (warp >> 1) * 32;
    const int n0 = (warp & 1) * 32;

    const uint32_t* phg = g_ph + ((size_t)bh * T_SEQ + t0) * 512;
    const uint32_t* plg = g_pl + ((size_t)bh * T_SEQ + t0) * 512;
    const uint32_t* vhg = g_vth + (size_t)bh * 64 * 512;
    const uint32_t* vlg = g_vtl + (size_t)bh * 64 * 512;

    int prow[2], pcol[2];
    #pragma unroll
    for (int i = 0; i < 2; i++) {
        int f = tid + i * 256;
        prow[i] = f >> 2;            // 0..127
        pcol[i] = (f & 3) * 4;       // 0,4,8,12
    }
    const int vrow = tid >> 2;       // 0..63
    const int vcol = (tid & 3) * 4;

    uint4 fph[2], fpl[2], fvh, fvl;

#define P2_FETCH(sp0)                                                          \
    _Pragma("unroll")                                                          \
    for (int i = 0; i < 2; i++) {                                              \
        size_t idx = (size_t)prow[i] * 512 + (sp0) + pcol[i];                  \
        fph[i] = *(const uint4*)&phg[idx];                                     \
        fpl[i] = *(const uint4*)&plg[idx];                                     \
    }                                                                          \
    {                                                                          \
        size_t idx = (size_t)vrow * 512 + (sp0) + vcol;                        \
        fvh = *(const uint4*)&vhg[idx];                                        \
        fvl = *(const uint4*)&vlg[idx];                                        \
    }

#define P2_STORE(bf)                                                           \
    _Pragma("unroll")                                                          \
    for (int i = 0; i < 2; i++) {                                              \
        int base = (bf) * PV_PB + prow[i] * PV_ROW + pcol[i];                  \
        *(uint4*)&Ph[base] = fph[i];                                           \
        *(uint4*)&Pl[base] = fpl[i];                                           \
    }                                                                          \
    {                                                                          \
        int base = (bf) * PV_VB + vrow * PV_ROW + vcol;                        \
        *(uint4*)&Vh[base] = fvh;                                              \
        *(uint4*)&Vl[base] = fvl;                                              \
    }

    float acc[2][4][4] = {};

#define P2_COMPUTE(bf)                                                         \
    _Pragma("unroll")                                                          \
    for (int ks = 0; ks < 2; ks++) {                                           \
        const int kc = ks * 8;                                                 \
        uint32_t bhf[4][2], blf[4][2];                                         \
        _Pragma("unroll")                                                      \
        for (int ni = 0; ni < 4; ni++) {                                       \
            int idx = (bf) * PV_VB + (n0 + ni * 8 + g) * PV_ROW + kc + t;      \
            bhf[ni][0] = Vh[idx]; bhf[ni][1] = Vh[idx + 4];                    \
            blf[ni][0] = Vl[idx]; blf[ni][1] = Vl[idx + 4];                    \
        }                                                                      \
        _Pragma("unroll")                                                      \
        for (int mi = 0; mi < 2; mi++) {                                       \
            int i1 = (bf) * PV_PB + (m0 + mi * 16 + g) * PV_ROW + kc + t;      \
            int i2 = i1 + 8 * PV_ROW;                                          \
            uint32_t ah[4], al[4];                                             \
            ah[0] = Ph[i1]; ah[1] = Ph[i2]; ah[2] = Ph[i1 + 4]; ah[3] = Ph[i2 + 4]; \
            al[0] = Pl[i1]; al[1] = Pl[i2]; al[2] = Pl[i1 + 4]; al[3] = Pl[i2 + 4]; \
            _Pragma("unroll")                                                  \
            for (int ni = 0; ni < 4; ni++) {                                   \
                MMA16816(acc[mi][ni], ah, bhf[ni])                             \
                MMA16816(acc[mi][ni], ah, blf[ni])                             \
                MMA16816(acc[mi][ni], al, bhf[ni])                             \
            }                                                                  \
        }                                                                      \
    }

    P2_FETCH(0)
    P2_STORE(0)
    __syncthreads();
    int buf = 0;
    for (int it = 1; it < 32; it++) {
        P2_FETCH(it * 16)
        P2_COMPUTE(buf)
        P2_STORE(buf ^ 1)
        __syncthreads();
        buf ^= 1;
    }
    P2_COMPUTE(buf)

    // epilogue: split attn pairs directly for the out-projection
    #pragma unroll
    for (int mi = 0; mi < 2; mi++) {
        const int rA = t0 + m0 + mi * 16 + g;
        #pragma unroll
        for (int ni = 0; ni < 4; ni++) {
            const int cc = n0 + ni * 8 + 2 * t;
            const size_t o0i = (size_t)rA * (BSZ * EMB / 2) + b * (EMB / 2) + ((h * HD + cc) >> 1);
            const size_t o1i = (size_t)(rA + 8) * (BSZ * EMB / 2) + b * (EMB / 2) + ((h * HD + cc) >> 1);
            uint32_t hh, ll;
            split_pair(acc[mi][ni][0], acc[mi][ni][1], hh, ll);
            g_ath[o0i] = hh; g_atl[o0i] = ll;
            split_pair(acc[mi][ni][2], acc[mi][ni][3], hh, ll);
            g_ath[o1i] = hh; g_atl[o1i] = ll;
        }
    }
}

// ============================================================
extern "C" void kernel_launch(void* const* d_in, const int* in_sizes, int n_in,
                              void* d_out, int out_size) {
    const float* query = (const float*)d_in[0];
    const float* w_in  = (const float*)d_in[1];
    const float* b_in  = (const float*)d_in[2];
    const float* w_out = (const float*)d_in[3];
    const float* b_out = (const float*)d_in[4];
    const float* rpk   = (const float*)d_in[5];
    float* out = (float*)d_out;

    void *pv_;
    float* p_qkv;   cudaGetSymbolAddress(&pv_, g_qkv);  p_qkv = (float*)pv_;
    uint32_t *qh, *ql, *wih, *wil, *woh, *wol, *ath, *atl;
    cudaGetSymbolAddress(&pv_, g_qh);  qh  = (uint32_t*)pv_;
    cudaGetSymbolAddress(&pv_, g_ql);  ql  = (uint32_t*)pv_;
    cudaGetSymbolAddress(&pv_, g_wih); wih = (uint32_t*)pv_;
    cudaGetSymbolAddress(&pv_, g_wil); wil = (uint32_t*)pv_;
    cudaGetSymbolAddress(&pv_, g_woh); woh = (uint32_t*)pv_;
    cudaGetSymbolAddress(&pv_, g_wol); wol = (uint32_t*)pv_;
    cudaGetSymbolAddress(&pv_, g_ath); ath = (uint32_t*)pv_;
    cudaGetSymbolAddress(&pv_, g_atl); atl = (uint32_t*)pv_;

    const int gemm_smem   = 8 * GT_BUF * sizeof(uint32_t);    // 81920
    const int scores_smem = 4 * SC_BUF * sizeof(uint32_t);    // 67584
    const int smax_smem   = 16 * SMPAD * sizeof(float);       // 65792
    const int pv_smem     = (4 * PV_PB + 4 * PV_VB) * sizeof(uint32_t);  // 61440
    cudaFuncSetAttribute(gemm_tc2, cudaFuncAttributeMaxDynamicSharedMemorySize, gemm_smem);
    cudaFuncSetAttribute(scores_tc, cudaFuncAttributeMaxDynamicSharedMemorySize, scores_smem);
    cudaFuncSetAttribute(softmax_avg_kernel, cudaFuncAttributeMaxDynamicSharedMemorySize, smax_smem);
    cudaFuncSetAttribute(pv_tc2, cudaFuncAttributeMaxDynamicSharedMemorySize, pv_smem);

    // 0. pre-split inputs / weights
    split_lin<<<8192, 256>>>(query, qh, ql);                  // 8192x1024
    split_lin<<<3072, 256>>>(w_in, wih, wil);                 // 3072x1024
    split_lin<<<1024, 256>>>(w_out, woh, wol);                // 1024x1024

    // 1. QKV projection (pre-split tensor-core GEMM)
    {
        dim3 grid(E3 / 128, (T_SEQ * BSZ) / 128);
        gemm_tc2<<<grid, 256, gemm_smem>>>(qh, ql, wih, wil, b_in, p_qkv,
                                           T_SEQ * BSZ, E3, EMB);
    }
    // 2. qrel table + V transpose/split
    {
        dim3 grid(T_SEQ, BH);
        qrel_kernel<<<grid, 128>>>(rpk);
    }
    {
        dim3 grid(T_SEQ / 64, BH);
        vt_split<<<grid, 256>>>();
    }
    // 3. scores
    {
        dim3 grid(T_SEQ / 128, T_SEQ / 128, BH);
        scores_tc<<<grid, 256, scores_smem>>>();
    }
    // 4. softmax -> split P + avg weights
    {
        dim3 grid(T_SEQ, BSZ);
        softmax_avg_kernel<<<grid, 256, smax_smem>>>(out + (size_t)T_SEQ * BSZ * EMB);
    }
    // 5. attn = P @ V -> split attn
    {
        dim3 grid(T_SEQ / 128, 1, BH);
        pv_tc2<<<grid, 256, pv_smem>>>();
    }
    // 6. out projection
    {
        dim3 grid(EMB / 128, (T_SEQ * BSZ) / 128);
        gemm_tc2<<<grid, 256, gemm_smem>>>(ath, atl, woh, wol, b_out, out,
                                           T_SEQ * BSZ, EMB, EMB);
    }
}

// round 12
// speedup vs baseline: 2.1512x; 1.0308x over previous
#include <cuda_runtime.h>
#include <cuda_bf16.h>
#include <cstdint>
#include <cstddef>

#define T_SEQ 1024
#define BSZ   8
#define EMB   1024
#define NH    16
#define HD    64
#define NR    33
#define E3    (3*EMB)
#define SCALE 0.125f
#define BH    (BSZ*NH)

// ---- scratch (static device globals; no allocations allowed) ----
__device__ float g_qkv[(size_t)T_SEQ * BSZ * E3];          // 96 MB  [T,B,3E]
__device__ float g_scores[(size_t)BH * T_SEQ * T_SEQ];     // 512 MB [BH,T,S]
__device__ float g_qrel[(size_t)BH * T_SEQ * NR];          // 16.5 MB
// pre-split operand buffers (packed bf16x2 hi/lo)
__device__ uint32_t g_qh[(size_t)8192 * 512];
__device__ uint32_t g_ql[(size_t)8192 * 512];
__device__ uint32_t g_wih[(size_t)3072 * 512];
__device__ uint32_t g_wil[(size_t)3072 * 512];
__device__ uint32_t g_woh[(size_t)1024 * 512];
__device__ uint32_t g_wol[(size_t)1024 * 512];
__device__ uint32_t g_ath[(size_t)8192 * 512];
__device__ uint32_t g_atl[(size_t)8192 * 512];
__device__ uint32_t g_vth[(size_t)BH * 64 * 512];
__device__ uint32_t g_vtl[(size_t)BH * 64 * 512];
__device__ uint32_t g_ph[(size_t)BH * T_SEQ * 512];
__device__ uint32_t g_pl[(size_t)BH * T_SEQ * 512];

// ============================================================
__device__ __forceinline__ uint32_t pack_bf(__nv_bfloat16 a, __nv_bfloat16 b) {
    return (uint32_t)__bfloat16_as_ushort(a) | ((uint32_t)__bfloat16_as_ushort(b) << 16);
}
__device__ __forceinline__ void split_pair(float x, float y, uint32_t& h, uint32_t& l) {
    __nv_bfloat16 hx = __float2bfloat16_rn(x), hy = __float2bfloat16_rn(y);
    h = pack_bf(hx, hy);
    __nv_bfloat16 lx = __float2bfloat16_rn(x - __bfloat162float(hx));
    __nv_bfloat16 ly = __float2bfloat16_rn(y - __bfloat162float(hy));
    l = pack_bf(lx, ly);
}
__device__ __forceinline__ uint32_t smem_u32(const void* p) {
    uint32_t a;
    asm("{ .reg .u64 u; cvta.to.shared.u64 u, %1; cvt.u32.u64 %0, u; }" : "=r"(a) : "l"(p));
    return a;
}

#define MMA16816(c, a, b)                                                     \
    asm volatile("mma.sync.aligned.m16n8k16.row.col.f32.bf16.bf16.f32 "       \
        "{%0,%1,%2,%3}, {%4,%5,%6,%7}, {%8,%9}, {%0,%1,%2,%3};"               \
        : "+f"((c)[0]), "+f"((c)[1]), "+f"((c)[2]), "+f"((c)[3])              \
        : "r"((a)[0]), "r"((a)[1]), "r"((a)[2]), "r"((a)[3]),                 \
          "r"((b)[0]), "r"((b)[1]));

#define LDSM4(r0, r1, r2, r3, a)                                              \
    asm volatile("ldmatrix.sync.aligned.m8n8.x4.shared.b16 {%0,%1,%2,%3}, [%4];" \
        : "=r"(r0), "=r"(r1), "=r"(r2), "=r"(r3) : "r"(a));

// ============================================================
// split_lin: fp32 src -> packed bf16x2 hi/lo
// ============================================================
__global__ void __launch_bounds__(256)
split_lin(const float* __restrict__ src, uint32_t* __restrict__ dh,
          uint32_t* __restrict__ dl) {
    size_t i = (size_t)blockIdx.x * 256 + threadIdx.x;
    float4 v = ((const float4*)src)[i];
    uint32_t h0, l0, h1, l1;
    split_pair(v.x, v.y, h0, l0);
    split_pair(v.z, v.w, h1, l1);
    uint2 ho = {h0, h1}, lo = {l0, l1};
    ((uint2*)dh)[i] = ho;
    ((uint2*)dl)[i] = lo;
}

// ============================================================
// vt_split: V (in g_qkv) -> transposed split  [bh][j][s-pair]
// ============================================================
__global__ void __launch_bounds__(256)
vt_split() {
    __shared__ float tile[64][68];
    const int s0 = blockIdx.x * 64;
    const int bh = blockIdx.y;
    const int b = bh >> 4, h = bh & 15;
    const size_t vbase = (size_t)b * E3 + 2 * EMB + h * HD;
    const int tid = threadIdx.x;

    #pragma unroll
    for (int i = 0; i < 4; i++) {
        int f = tid + i * 256;
        int row = f >> 4;
        int col = (f & 15) * 4;
        float4 v = *(const float4*)&g_qkv[(size_t)(s0 + row) * BSZ * E3 + vbase + col];
        *(float4*)&tile[row][col] = v;
    }
    __syncthreads();

    const int j = tid >> 2;
    const int spq = (tid & 3) * 8;
    const size_t obase = ((size_t)bh * 64 + j) * 512 + (s0 >> 1);
    #pragma unroll
    for (int q = 0; q < 8; q++) {
        int sl = 2 * (spq + q);
        uint32_t hh, ll;
        split_pair(tile[sl][j], tile[sl + 1][j], hh, ll);
        g_vth[obase + spq + q] = hh;
        g_vtl[obase + spq + q] = ll;
    }
}

// ============================================================
// gemm_tc2: C = A@W^T + bias from PRE-SPLIT operands, ldmatrix frags.
// ============================================================
#define GT_ROW 20
#define GT_BUF (128 * GT_ROW)

__global__ void __launch_bounds__(256)
gemm_tc2(const uint32_t* __restrict__ Ahg, const uint32_t* __restrict__ Alg,
         const uint32_t* __restrict__ Whg, const uint32_t* __restrict__ Wlg,
         const float* __restrict__ bias, float* __restrict__ C,
         int M, int N, int K) {
    extern __shared__ uint32_t sm[];
    uint32_t* Ah = sm;
    uint32_t* Al = sm + 2 * GT_BUF;
    uint32_t* Wh = sm + 4 * GT_BUF;
    uint32_t* Wl = sm + 6 * GT_BUF;

    const int tid  = threadIdx.x;
    const int warp = tid >> 5, lane = tid & 31;
    const int g = lane >> 2, t = lane & 3;
    const int m0 = (warp >> 2) * 64;
    const int n0 = (warp & 3) * 32;
    const int row0 = blockIdx.y * 128, col0 = blockIdx.x * 128;
    const int K2 = K >> 1;

    const uint32_t smb = smem_u32(sm);
    const int a_loff = (lane & 15) * GT_ROW + (lane >> 4) * 4;
    const int b_loff = (((lane >> 4) << 3) + (lane & 7)) * GT_ROW + ((lane >> 3) & 1) * 4;

    int frow[2], fcol[2];
    #pragma unroll
    for (int i = 0; i < 2; i++) {
        int f = tid + i * 256;
        frow[i] = f >> 2;
        fcol[i] = (f & 3) * 4;
    }

    uint4 pah[2], pal[2], pwh[2], pwl[2];

#define G2_FETCH(k0)                                                           \
    _Pragma("unroll")                                                          \
    for (int i = 0; i < 2; i++) {                                              \
        size_t ar = (size_t)(row0 + frow[i]) * K2 + ((k0) >> 1) + fcol[i];     \
        size_t wr = (size_t)(col0 + frow[i]) * K2 + ((k0) >> 1) + fcol[i];     \
        pah[i] = *(const uint4*)&Ahg[ar];                                      \
        pal[i] = *(const uint4*)&Alg[ar];                                      \
        pwh[i] = *(const uint4*)&Whg[wr];                                      \
        pwl[i] = *(const uint4*)&Wlg[wr];                                      \
    }

#define G2_STORE(bf)                                                           \
    _Pragma("unroll")                                                          \
    for (int i = 0; i < 2; i++) {                                              \
        int base = (bf) * GT_BUF + frow[i] * GT_ROW + fcol[i];                 \
        *(uint4*)&Ah[base] = pah[i];                                           \
        *(uint4*)&Al[base] = pal[i];                                           \
        *(uint4*)&Wh[base] = pwh[i];                                           \
        *(uint4*)&Wl[base] = pwl[i];                                           \
    }

    float acc[4][4][4] = {};

#define G2_COMPUTE(bf)                                                         \
    _Pragma("unroll")                                                          \
    for (int ks = 0; ks < 2; ks++) {                                           \
        const int kc = ks * 8;                                                 \
        uint32_t bhf[4][2], blf[4][2];                                         \
        _Pragma("unroll")                                                      \
        for (int np = 0; np < 2; np++) {                                       \
            uint32_t aw = smb + 4u * (4 * GT_BUF + (bf) * GT_BUF               \
                        + (n0 + np * 16) * GT_ROW + kc + b_loff);              \
            LDSM4(bhf[2*np][0], bhf[2*np][1], bhf[2*np+1][0], bhf[2*np+1][1], aw) \
            LDSM4(blf[2*np][0], blf[2*np][1], blf[2*np+1][0], blf[2*np+1][1],  \
                  aw + 4u * 2 * GT_BUF)                                        \
        }                                                                      \
        _Pragma("unroll")                                                      \
        for (int mi = 0; mi < 4; mi++) {                                       \
            uint32_t ah[4], al[4];                                             \
            uint32_t aa = smb + 4u * ((bf) * GT_BUF                            \
                        + (m0 + mi * 16) * GT_ROW + kc + a_loff);              \
            LDSM4(ah[0], ah[1], ah[2], ah[3], aa)                              \
            LDSM4(al[0], al[1], al[2], al[3], aa + 4u * 2 * GT_BUF)            \
            _Pragma("unroll")                                                  \
            for (int ni = 0; ni < 4; ni++) {                                   \
                MMA16816(acc[mi][ni], ah, bhf[ni])                             \
                MMA16816(acc[mi][ni], ah, blf[ni])                             \
                MMA16816(acc[mi][ni], al, bhf[ni])                             \
            }                                                                  \
        }                                                                      \
    }

    G2_FETCH(0)
    G2_STORE(0)
    __syncthreads();
    int buf = 0;
    const int nk = K >> 5;
    for (int it = 1; it < nk; it++) {
        G2_FETCH(it * 32)
        G2_COMPUTE(buf)
        G2_STORE(buf ^ 1)
        __syncthreads();
        buf ^= 1;
    }
    G2_COMPUTE(buf)

    #pragma unroll
    for (int mi = 0; mi < 4; mi++) {
        const int rA = row0 + m0 + mi * 16 + g;
        #pragma unroll
        for (int ni = 0; ni < 4; ni++) {
            const int cc = col0 + n0 + ni * 8 + 2 * t;
            const float b0 = bias[cc], b1 = bias[cc + 1];
            float2 o0 = { acc[mi][ni][0] + b0, acc[mi][ni][1] + b1 };
            float2 o1 = { acc[mi][ni][2] + b0, acc[mi][ni][3] + b1 };
            *(float2*)&C[(size_t)rA * N + cc] = o0;
            *(float2*)&C[(size_t)(rA + 8) * N + cc] = o1;
        }
    }
}

// ============================================================
// qrel[bh, t, r] = SCALE * sum_j q[t,b,h*64+j] * rpk[r, j]
// ============================================================
__global__ void __launch_bounds__(128)
qrel_kernel(const float* __restrict__ rpk) {
    const int t = blockIdx.x;
    const int bh = blockIdx.y;
    const int b = bh >> 4, h = bh & 15;
    __shared__ float qs[HD];
    __shared__ float rs[NR * HD];
    const int tid = threadIdx.x;
    if (tid < HD)
        qs[tid] = g_qkv[(size_t)t * BSZ * E3 + (size_t)b * E3 + h * HD + tid] * SCALE;
    for (int i = tid; i < NR * HD; i += 128) rs[i] = rpk[i];
    __syncthreads();
    if (tid < NR) {
        float s = 0.f;
        #pragma unroll
        for (int j = 0; j < HD; j++) s += qs[j] * rs[tid * HD + j];
        g_qrel[((size_t)bh * T_SEQ + t) * NR + tid] = s;
    }
}

// ============================================================
// scores_tc: scores = (SCALE*q)·k + qrel lookup; ldmatrix frags.
// SC_ROW=36 (16B-aligned rows for LDSM, conflict-free).
// ============================================================
#define SC_ROW 36
#define SC_BUF (128 * SC_ROW)

__global__ void __launch_bounds__(256)
scores_tc() {
    extern __shared__ uint32_t sm[];
    uint32_t* Qh = sm;
    uint32_t* Ql = sm + SC_BUF;
    uint32_t* Kh = sm + 2 * SC_BUF;
    uint32_t* Kl = sm + 3 * SC_BUF;

    const int bh = blockIdx.z;
    const int b = bh >> 4, h = bh & 15;
    const int t0 = blockIdx.y * 128, s0 = blockIdx.x * 128;
    const int tid = threadIdx.x;
    const int warp = tid >> 5, lane = tid & 31;
    const int g = lane >> 2, t = lane & 3;
    const int m0 = (warp >> 2) * 64;
    const int n0 = (warp & 3) * 32;
    const size_t qoff = (size_t)b * E3 + h * HD;

    const uint32_t smb = smem_u32(sm);
    const int a_loff = (lane & 15) * SC_ROW + (lane >> 4) * 4;
    const int b_loff = (((lane >> 4) << 3) + (lane & 7)) * SC_ROW + ((lane >> 3) & 1) * 4;

    #pragma unroll
    for (int i = 0; i < 8; i++) {
        int f = tid + i * 256;
        int row = f >> 4;
        int c = (f & 15) * 4;
        float4 q = *(const float4*)&g_qkv[(size_t)(t0 + row) * BSZ * E3 + qoff + c];
        float4 k = *(const float4*)&g_qkv[(size_t)(s0 + row) * BSZ * E3 + qoff + EMB + c];
        int base = row * SC_ROW + (c >> 1);
        uint32_t h0, l0, h1, l1;
        split_pair(q.x * SCALE, q.y * SCALE, h0, l0);
        split_pair(q.z * SCALE, q.w * SCALE, h1, l1);
        Qh[base] = h0; Qh[base + 1] = h1;
        Ql[base] = l0; Ql[base + 1] = l1;
        split_pair(k.x, k.y, h0, l0);
        split_pair(k.z, k.w, h1, l1);
        Kh[base] = h0; Kh[base + 1] = h1;
        Kl[base] = l0; Kl[base + 1] = l1;
    }
    __syncthreads();

    float acc[4][4][4] = {};
    #pragma unroll
    for (int kc = 0; kc < 32; kc += 8) {
        uint32_t bhf[4][2], blf[4][2];
        #pragma unroll
        for (int np = 0; np < 2; np++) {
            uint32_t aw = smb + 4u * (2 * SC_BUF + (n0 + np * 16) * SC_ROW + kc + b_loff);
            LDSM4(bhf[2*np][0], bhf[2*np][1], bhf[2*np+1][0], bhf[2*np+1][1], aw)
            LDSM4(blf[2*np][0], blf[2*np][1], blf[2*np+1][0], blf[2*np+1][1],
                  aw + 4u * SC_BUF)
        }
        #pragma unroll
        for (int mi = 0; mi < 4; mi++) {
            uint32_t ah[4], al[4];
            uint32_t aa = smb + 4u * ((m0 + mi * 16) * SC_ROW + kc + a_loff);
            LDSM4(ah[0], ah[1], ah[2], ah[3], aa)
            LDSM4(al[0], al[1], al[2], al[3], aa + 4u * SC_BUF)
            #pragma unroll
            for (int ni = 0; ni < 4; ni++) {
                MMA16816(acc[mi][ni], ah, bhf[ni])
                MMA16816(acc[mi][ni], ah, blf[ni])
                MMA16816(acc[mi][ni], al, bhf[ni])
            }
        }
    }

    #pragma unroll
    for (int mi = 0; mi < 4; mi++) {
        #pragma unroll
        for (int rr = 0; rr < 2; rr++) {
            const int tI = t0 + m0 + mi * 16 + g + rr * 8;
            const float* qr_row = &g_qrel[((size_t)bh * T_SEQ + tI) * NR];
            float* orow = &g_scores[((size_t)bh * T_SEQ + tI) * T_SEQ];
            #pragma unroll
            for (int ni = 0; ni < 4; ni++) {
                const int sI = s0 + n0 + ni * 8 + 2 * t;
                int d0 = sI - tI;     d0 = d0 < -16 ? -16 : (d0 > 16 ? 16 : d0);
                int d1 = sI + 1 - tI; d1 = d1 < -16 ? -16 : (d1 > 16 ? 16 : d1);
                float2 o;
                o.x = acc[mi][ni][rr * 2 + 0] + qr_row[d0 + 16];
                o.y = acc[mi][ni][rr * 2 + 1] + qr_row[d1 + 16];
                *(float2*)&orow[sI] = o;
            }
        }
    }
}

// ============================================================
// Fused softmax + avg; writes P as SPLIT bf16x2 hi/lo.
// ============================================================
#define SMPAD 1028
__global__ void __launch_bounds__(256)
softmax_avg_kernel(float* __restrict__ avg) {
    extern __shared__ float S[];
    const int t = blockIdx.x;
    const int b = blockIdx.y;
    const int tid = threadIdx.x;
    const int warp = tid >> 5, lane = tid & 31;

    #pragma unroll
    for (int rep = 0; rep < 2; rep++) {
        const int h = warp + rep * 8;
        const size_t prow = ((size_t)(b * NH + h)) * T_SEQ + t;
        const float* row = g_scores + prow * T_SEQ;
        float4 v[8];
        #pragma unroll
        for (int i = 0; i < 8; i++)
            v[i] = *(const float4*)&row[lane * 4 + i * 128];

        float m = -1e30f;
        #pragma unroll
        for (int i = 0; i < 8; i++)
            m = fmaxf(m, fmaxf(fmaxf(v[i].x, v[i].y), fmaxf(v[i].z, v[i].w)));
        #pragma unroll
        for (int o = 16; o; o >>= 1) m = fmaxf(m, __shfl_xor_sync(0xffffffffu, m, o));

        float ssum = 0.f;
        #pragma unroll
        for (int i = 0; i < 8; i++) {
            v[i].x = __expf(v[i].x - m); v[i].y = __expf(v[i].y - m);
            v[i].z = __expf(v[i].z - m); v[i].w = __expf(v[i].w - m);
            ssum += v[i].x + v[i].y + v[i].z + v[i].w;
        }
        #pragma unroll
        for (int o = 16; o; o >>= 1) ssum += __shfl_xor_sync(0xffffffffu, ssum, o);
        const float inv = 1.0f / ssum;

        float* srow = &S[(size_t)h * SMPAD];
        uint32_t* ph = g_ph + prow * 512;
        uint32_t* pl = g_pl + prow * 512;
        #pragma unroll
        for (int i = 0; i < 8; i++) {
            v[i].x *= inv; v[i].y *= inv; v[i].z *= inv; v[i].w *= inv;
            *(float4*)&srow[lane * 4 + i * 128] = v[i];
            uint32_t h0, l0, h1, l1;
            split_pair(v[i].x, v[i].y, h0, l0);
            split_pair(v[i].z, v[i].w, h1, l1);
            uint2 ho = {h0, h1}, lo = {l0, l1};
            *(uint2*)&ph[lane * 2 + i * 64] = ho;
            *(uint2*)&pl[lane * 2 + i * 64] = lo;
        }
    }
    __syncthreads();

    const int c = tid * 4;
    float4 acc = make_float4(0.f, 0.f, 0.f, 0.f);
    #pragma unroll
    for (int h = 0; h < NH; h++) {
        float4 v = *(const float4*)&S[(size_t)h * SMPAD + c];
        acc.x += v.x; acc.y += v.y; acc.z += v.z; acc.w += v.w;
    }
    const float invh = 1.0f / NH;
    acc.x *= invh; acc.y *= invh; acc.z *= invh; acc.w *= invh;
    *(float4*)&avg[(((size_t)b * T_SEQ + t) * T_SEQ) + c] = acc;
}

// ============================================================
// pv_tc2: attn = P @ V from pre-split inputs; ldmatrix frags.
// ============================================================
#define PV_ROW 20
#define PV_PB (128 * PV_ROW)
#define PV_VB (64 * PV_ROW)

__global__ void __launch_bounds__(256)
pv_tc2() {
    extern __shared__ uint32_t sm[];
    uint32_t* Ph = sm;
    uint32_t* Pl = sm + 2 * PV_PB;
    uint32_t* Vh = sm + 4 * PV_PB;
    uint32_t* Vl = sm + 4 * PV_PB + 2 * PV_VB;

    const int bh = blockIdx.z;
    const int b = bh >> 4, h = bh & 15;
    const int t0 = blockIdx.x * 128;
    const int tid = threadIdx.x;
    const int warp = tid >> 5, lane = tid & 31;
    const int g = lane >> 2, t = lane & 3;
    const int m0 = (warp >> 1) * 32;
    const int n0 = (warp & 1) * 32;

    const uint32_t* phg = g_ph + ((size_t)bh * T_SEQ + t0) * 512;
    const uint32_t* plg = g_pl + ((size_t)bh * T_SEQ + t0) * 512;
    const uint32_t* vhg = g_vth + (size_t)bh * 64 * 512;
    const uint32_t* vlg = g_vtl + (size_t)bh * 64 * 512;

    const uint32_t smb = smem_u32(sm);
    const int a_loff = (lane & 15) * PV_ROW + (lane >> 4) * 4;
    const int b_loff = (((lane >> 4) << 3) + (lane & 7)) * PV_ROW + ((lane >> 3) & 1) * 4;

    int prow[2], pcol[2];
    #pragma unroll
    for (int i = 0; i < 2; i++) {
        int f = tid + i * 256;
        prow[i] = f >> 2;
        pcol[i] = (f & 3) * 4;
    }
    const int vrow = tid >> 2;
    const int vcol = (tid & 3) * 4;

    uint4 fph[2], fpl[2], fvh, fvl;

#define P2_FETCH(sp0)                                                          \
    _Pragma("unroll")                                                          \
    for (int i = 0; i < 2; i++) {                                              \
        size_t idx = (size_t)prow[i] * 512 + (sp0) + pcol[i];                  \
        fph[i] = *(const uint4*)&phg[idx];                                     \
        fpl[i] = *(const uint4*)&plg[idx];                                     \
    }                                                                          \
    {                                                                          \
        size_t idx = (size_t)vrow * 512 + (sp0) + vcol;                        \
        fvh = *(const uint4*)&vhg[idx];                                        \
        fvl = *(const uint4*)&vlg[idx];                                        \
    }

#define P2_STORE(bf)                                                           \
    _Pragma("unroll")                                                          \
    for (int i = 0; i < 2; i++) {                                              \
        int base = (bf) * PV_PB + prow[i] * PV_ROW + pcol[i];                  \
        *(uint4*)&Ph[base] = fph[i];                                           \
        *(uint4*)&Pl[base] = fpl[i];                                           \
    }                                                                          \
    {                                                                          \
        int base = (bf) * PV_VB + vrow * PV_ROW + vcol;                        \
        *(uint4*)&Vh[base] = fvh;                                              \
        *(uint4*)&Vl[base] = fvl;                                              \
    }

    float acc[2][4][4] = {};

#define P2_COMPUTE(bf)                                                         \
    _Pragma("unroll")                                                          \
    for (int ks = 0; ks < 2; ks++) {                                           \
        const int kc = ks * 8;                                                 \
        uint32_t bhf[4][2], blf[4][2];                                         \
        _Pragma("unroll")                                                      \
        for (int np = 0; np < 2; np++) {                                       \
            uint32_t aw = smb + 4u * (4 * PV_PB + (bf) * PV_VB                 \
                        + (n0 + np * 16) * PV_ROW + kc + b_loff);              \
            LDSM4(bhf[2*np][0], bhf[2*np][1], bhf[2*np+1][0], bhf[2*np+1][1], aw) \
            LDSM4(blf[2*np][0], blf[2*np][1], blf[2*np+1][0], blf[2*np+1][1],  \
                  aw + 4u * 2 * PV_VB)                                         \
        }                                                                      \
        _Pragma("unroll")                                                      \
        for (int mi = 0; mi < 2; mi++) {                                       \
            uint32_t ah[4], al[4];                                             \
            uint32_t aa = smb + 4u * ((bf) * PV_PB                             \
                        + (m0 + mi * 16) * PV_ROW + kc + a_loff);              \
            LDSM4(ah[0], ah[1], ah[2], ah[3], aa)                              \
            LDSM4(al[0], al[1], al[2], al[3], aa + 4u * 2 * PV_PB)             \
            _Pragma("unroll")                                                  \
            for (int ni = 0; ni < 4; ni++) {                                   \
                MMA16816(acc[mi][ni], ah, bhf[ni])                             \
                MMA16816(acc[mi][ni], ah, blf[ni])                             \
                MMA16816(acc[mi][ni], al, bhf[ni])                             \
            }                                                                  \
        }                                                                      \
    }

    P2_FETCH(0)
    P2_STORE(0)
    __syncthreads();
    int buf = 0;
    for (int it = 1; it < 32; it++) {
        P2_FETCH(it * 16)
        P2_COMPUTE(buf)
        P2_STORE(buf ^ 1)
        __syncthreads();
        buf ^= 1;
    }
    P2_COMPUTE(buf)

    #pragma unroll
    for (int mi = 0; mi < 2; mi++) {
        const int rA = t0 + m0 + mi * 16 + g;
        #pragma unroll
        for (int ni = 0; ni < 4; ni++) {
            const int cc = n0 + ni * 8 + 2 * t;
            const size_t o0i = (size_t)rA * (BSZ * EMB / 2) + b * (EMB / 2) + ((h * HD + cc) >> 1);
            const size_t o1i = (size_t)(rA + 8) * (BSZ * EMB / 2) + b * (EMB / 2) + ((h * HD + cc) >> 1);
            uint32_t hh, ll;
            split_pair(acc[mi][ni][0], acc[mi][ni][1], hh, ll);
            g_ath[o0i] = hh; g_atl[o0i] = ll;
            split_pair(acc[mi][ni][2], acc[mi][ni][3], hh, ll);
            g_ath[o1i] = hh; g_atl[o1i] = ll;
        }
    }
}

// ============================================================
extern "C" void kernel_launch(void* const* d_in, const int* in_sizes, int n_in,
                              void* d_out, int out_size) {
    const float* query = (const float*)d_in[0];
    const float* w_in  = (const float*)d_in[1];
    const float* b_in  = (const float*)d_in[2];
    const float* w_out = (const float*)d_in[3];
    const float* b_out = (const float*)d_in[4];
    const float* rpk   = (const float*)d_in[5];
    float* out = (float*)d_out;

    void *pv_;
    float* p_qkv;   cudaGetSymbolAddress(&pv_, g_qkv);  p_qkv = (float*)pv_;
    uint32_t *qh, *ql, *wih, *wil, *woh, *wol, *ath, *atl;
    cudaGetSymbolAddress(&pv_, g_qh);  qh  = (uint32_t*)pv_;
    cudaGetSymbolAddress(&pv_, g_ql);  ql  = (uint32_t*)pv_;
    cudaGetSymbolAddress(&pv_, g_wih); wih = (uint32_t*)pv_;
    cudaGetSymbolAddress(&pv_, g_wil); wil = (uint32_t*)pv_;
    cudaGetSymbolAddress(&pv_, g_woh); woh = (uint32_t*)pv_;
    cudaGetSymbolAddress(&pv_, g_wol); wol = (uint32_t*)pv_;
    cudaGetSymbolAddress(&pv_, g_ath); ath = (uint32_t*)pv_;
    cudaGetSymbolAddress(&pv_, g_atl); atl = (uint32_t*)pv_;

    const int gemm_smem   = 8 * GT_BUF * sizeof(uint32_t);    // 81920
    const int scores_smem = 4 * SC_BUF * sizeof(uint32_t);    // 73728
    const int smax_smem   = 16 * SMPAD * sizeof(float);       // 65792
    const int pv_smem     = (4 * PV_PB + 4 * PV_VB) * sizeof(uint32_t);  // 61440
    cudaFuncSetAttribute(gemm_tc2, cudaFuncAttributeMaxDynamicSharedMemorySize, gemm_smem);
    cudaFuncSetAttribute(scores_tc, cudaFuncAttributeMaxDynamicSharedMemorySize, scores_smem);
    cudaFuncSetAttribute(softmax_avg_kernel, cudaFuncAttributeMaxDynamicSharedMemorySize, smax_smem);
    cudaFuncSetAttribute(pv_tc2, cudaFuncAttributeMaxDynamicSharedMemorySize, pv_smem);

    // 0. pre-split inputs / weights
    split_lin<<<8192, 256>>>(query, qh, ql);
    split_lin<<<3072, 256>>>(w_in, wih, wil);
    split_lin<<<1024, 256>>>(w_out, woh, wol);

    // 1. QKV projection
    {
        dim3 grid(E3 / 128, (T_SEQ * BSZ) / 128);
        gemm_tc2<<<grid, 256, gemm_smem>>>(qh, ql, wih, wil, b_in, p_qkv,
                                           T_SEQ * BSZ, E3, EMB);
    }
    // 2. qrel table + V transpose/split
    {
        dim3 grid(T_SEQ, BH);
        qrel_kernel<<<grid, 128>>>(rpk);
    }
    {
        dim3 grid(T_SEQ / 64, BH);
        vt_split<<<grid, 256>>>();
    }
    // 3. scores
    {
        dim3 grid(T_SEQ / 128, T_SEQ / 128, BH);
        scores_tc<<<grid, 256, scores_smem>>>();
    }
    // 4. softmax -> split P + avg weights
    {
        dim3 grid(T_SEQ, BSZ);
        softmax_avg_kernel<<<grid, 256, smax_smem>>>(out + (size_t)T_SEQ * BSZ * EMB);
    }
    // 5. attn = P @ V -> split attn
    {
        dim3 grid(T_SEQ / 128, 1, BH);
        pv_tc2<<<grid, 256, pv_smem>>>();
    }
    // 6. out projection
    {
        dim3 grid(EMB / 128, (T_SEQ * BSZ) / 128);
        gemm_tc2<<<grid, 256, gemm_smem>>>(ath, atl, woh, wol, b_out, out,
                                           T_SEQ * BSZ, EMB, EMB);
    }
}

// round 14
// speedup vs baseline: 2.4500x; 1.1389x over previous
#include <cuda_runtime.h>
#include <cuda_bf16.h>
#include <cstdint>
#include <cstddef>

#define T_SEQ 1024
#define BSZ   8
#define EMB   1024
#define NH    16
#define HD    64
#define NR    33
#define E3    (3*EMB)
#define SCALE 0.125f
#define BH    (BSZ*NH)

// ---- scratch (static device globals; no allocations allowed) ----
__device__ float g_qkv[(size_t)T_SEQ * BSZ * E3];          // 96 MB  [T,B,3E]
__device__ float g_scores[(size_t)BH * T_SEQ * T_SEQ];     // 512 MB [BH,T,S]
__device__ float g_qrel[(size_t)BH * T_SEQ * NR];          // 16.5 MB
// pre-split operand buffers (packed bf16x2 hi/lo)
__device__ uint32_t g_qh[(size_t)8192 * 512];
__device__ uint32_t g_ql[(size_t)8192 * 512];
__device__ uint32_t g_wih[(size_t)3072 * 512];
__device__ uint32_t g_wil[(size_t)3072 * 512];
__device__ uint32_t g_woh[(size_t)1024 * 512];
__device__ uint32_t g_wol[(size_t)1024 * 512];
__device__ uint32_t g_ath[(size_t)8192 * 512];
__device__ uint32_t g_atl[(size_t)8192 * 512];
__device__ uint32_t g_vth[(size_t)BH * 64 * 512];
__device__ uint32_t g_vtl[(size_t)BH * 64 * 512];
__device__ uint32_t g_ph[(size_t)BH * T_SEQ * 512];
__device__ uint32_t g_pl[(size_t)BH * T_SEQ * 512];

// ============================================================
__device__ __forceinline__ uint32_t pack_bf(__nv_bfloat16 a, __nv_bfloat16 b) {
    return (uint32_t)__bfloat16_as_ushort(a) | ((uint32_t)__bfloat16_as_ushort(b) << 16);
}
__device__ __forceinline__ void split_pair(float x, float y, uint32_t& h, uint32_t& l) {
    __nv_bfloat16 hx = __float2bfloat16_rn(x), hy = __float2bfloat16_rn(y);
    h = pack_bf(hx, hy);
    __nv_bfloat16 lx = __float2bfloat16_rn(x - __bfloat162float(hx));
    __nv_bfloat16 ly = __float2bfloat16_rn(y - __bfloat162float(hy));
    l = pack_bf(lx, ly);
}
__device__ __forceinline__ uint32_t smem_u32(const void* p) {
    uint32_t a;
    asm("{ .reg .u64 u; cvta.to.shared.u64 u, %1; cvt.u32.u64 %0, u; }" : "=r"(a) : "l"(p));
    return a;
}

#define MMA16816(c, a, b)                                                     \
    asm volatile("mma.sync.aligned.m16n8k16.row.col.f32.bf16.bf16.f32 "       \
        "{%0,%1,%2,%3}, {%4,%5,%6,%7}, {%8,%9}, {%0,%1,%2,%3};"               \
        : "+f"((c)[0]), "+f"((c)[1]), "+f"((c)[2]), "+f"((c)[3])              \
        : "r"((a)[0]), "r"((a)[1]), "r"((a)[2]), "r"((a)[3]),                 \
          "r"((b)[0]), "r"((b)[1]));

#define LDSM4(r0, r1, r2, r3, a)                                              \
    asm volatile("ldmatrix.sync.aligned.m8n8.x4.shared.b16 {%0,%1,%2,%3}, [%4];" \
        : "=r"(r0), "=r"(r1), "=r"(r2), "=r"(r3) : "r"(a));

#define CP_ASYNC16(sa, gp)                                                    \
    asm volatile("cp.async.cg.shared.global [%0], [%1], 16;" :: "r"(sa), "l"(gp));
#define CP_COMMIT  asm volatile("cp.async.commit_group;" ::: "memory");
#define CP_WAIT0   asm volatile("cp.async.wait_group 0;" ::: "memory");

// ============================================================
// split_lin: fp32 src -> packed bf16x2 hi/lo
// ============================================================
__global__ void __launch_bounds__(256)
split_lin(const float* __restrict__ src, uint32_t* __restrict__ dh,
          uint32_t* __restrict__ dl) {
    size_t i = (size_t)blockIdx.x * 256 + threadIdx.x;
    float4 v = ((const float4*)src)[i];
    uint32_t h0, l0, h1, l1;
    split_pair(v.x, v.y, h0, l0);
    split_pair(v.z, v.w, h1, l1);
    uint2 ho = {h0, h1}, lo = {l0, l1};
    ((uint2*)dh)[i] = ho;
    ((uint2*)dl)[i] = lo;
}

// ============================================================
// vt_split: V (in g_qkv) -> transposed split  [bh][j][s-pair]
// ============================================================
__global__ void __launch_bounds__(256)
vt_split() {
    __shared__ float tile[64][68];
    const int s0 = blockIdx.x * 64;
    const int bh = blockIdx.y;
    const int b = bh >> 4, h = bh & 15;
    const size_t vbase = (size_t)b * E3 + 2 * EMB + h * HD;
    const int tid = threadIdx.x;

    #pragma unroll
    for (int i = 0; i < 4; i++) {
        int f = tid + i * 256;
        int row = f >> 4;
        int col = (f & 15) * 4;
        float4 v = *(const float4*)&g_qkv[(size_t)(s0 + row) * BSZ * E3 + vbase + col];
        *(float4*)&tile[row][col] = v;
    }
    __syncthreads();

    const int j = tid >> 2;
    const int spq = (tid & 3) * 8;
    const size_t obase = ((size_t)bh * 64 + j) * 512 + (s0 >> 1);
    #pragma unroll
    for (int q = 0; q < 8; q++) {
        int sl = 2 * (spq + q);
        uint32_t hh, ll;
        split_pair(tile[sl][j], tile[sl + 1][j], hh, ll);
        g_vth[obase + spq + q] = hh;
        g_vtl[obase + spq + q] = ll;
    }
}

// ============================================================
// gemm_tc2: C = A@W^T + bias, pre-split operands, cp.async + ldmatrix.
// 2 CTAs/SM target.
// ============================================================
#define GT_ROW 20
#define GT_BUF (128 * GT_ROW)

__global__ void __launch_bounds__(256, 2)
gemm_tc2(const uint32_t* __restrict__ Ahg, const uint32_t* __restrict__ Alg,
         const uint32_t* __restrict__ Whg, const uint32_t* __restrict__ Wlg,
         const float* __restrict__ bias, float* __restrict__ C,
         int M, int N, int K) {
    extern __shared__ uint32_t sm[];

    const int tid  = threadIdx.x;
    const int warp = tid >> 5, lane = tid & 31;
    const int g = lane >> 2, t = lane & 3;
    const int m0 = (warp >> 2) * 64;
    const int n0 = (warp & 3) * 32;
    const int row0 = blockIdx.y * 128, col0 = blockIdx.x * 128;
    const int K2 = K >> 1;

    const uint32_t smb = smem_u32(sm);
    const int a_loff = (lane & 15) * GT_ROW + (lane >> 4) * 4;
    const int b_loff = (((lane >> 4) << 3) + (lane & 7)) * GT_ROW + ((lane >> 3) & 1) * 4;

    int frow[2], fcol[2];
    #pragma unroll
    for (int i = 0; i < 2; i++) {
        int f = tid + i * 256;
        frow[i] = f >> 2;
        fcol[i] = (f & 3) * 4;
    }

// async fetch one BK32 stage into buffer bf (Ah|Al|Wh|Wl each 128x20)
#define G2_PREFETCH(bf, k0)                                                    \
    _Pragma("unroll")                                                          \
    for (int i = 0; i < 2; i++) {                                              \
        size_t ar = (size_t)(row0 + frow[i]) * K2 + ((k0) >> 1) + fcol[i];     \
        size_t wr = (size_t)(col0 + frow[i]) * K2 + ((k0) >> 1) + fcol[i];     \
        uint32_t sb = smb + 4u * ((bf) * GT_BUF + frow[i] * GT_ROW + fcol[i]); \
        CP_ASYNC16(sb,                    Ahg + ar)                            \
        CP_ASYNC16(sb + 4u * 2 * GT_BUF,  Alg + ar)                            \
        CP_ASYNC16(sb + 4u * 4 * GT_BUF,  Whg + wr)                            \
        CP_ASYNC16(sb + 4u * 6 * GT_BUF,  Wlg + wr)                            \
    }

    float acc[4][4][4] = {};

#define G2_COMPUTE(bf)                                                         \
    _Pragma("unroll")                                                          \
    for (int ks = 0; ks < 2; ks++) {                                           \
        const int kc = ks * 8;                                                 \
        uint32_t bhf[4][2], blf[4][2];                                         \
        _Pragma("unroll")                                                      \
        for (int np = 0; np < 2; np++) {                                       \
            uint32_t aw = smb + 4u * (4 * GT_BUF + (bf) * GT_BUF               \
                        + (n0 + np * 16) * GT_ROW + kc + b_loff);              \
            LDSM4(bhf[2*np][0], bhf[2*np][1], bhf[2*np+1][0], bhf[2*np+1][1], aw) \
            LDSM4(blf[2*np][0], blf[2*np][1], blf[2*np+1][0], blf[2*np+1][1],  \
                  aw + 4u * 2 * GT_BUF)                                        \
        }                                                                      \
        _Pragma("unroll")                                                      \
        for (int mi = 0; mi < 4; mi++) {                                       \
            uint32_t ah[4], al[4];                                             \
            uint32_t aa = smb + 4u * ((bf) * GT_BUF                            \
                        + (m0 + mi * 16) * GT_ROW + kc + a_loff);              \
            LDSM4(ah[0], ah[1], ah[2], ah[3], aa)                              \
            LDSM4(al[0], al[1], al[2], al[3], aa + 4u * 2 * GT_BUF)            \
            _Pragma("unroll")                                                  \
            for (int ni = 0; ni < 4; ni++) {                                   \
                MMA16816(acc[mi][ni], ah, bhf[ni])                             \
                MMA16816(acc[mi][ni], ah, blf[ni])                             \
                MMA16816(acc[mi][ni], al, bhf[ni])                             \
            }                                                                  \
        }                                                                      \
    }

    G2_PREFETCH(0, 0)
    CP_COMMIT
    CP_WAIT0
    __syncthreads();
    int buf = 0;
    const int nk = K >> 5;
    for (int it = 1; it < nk; it++) {
        G2_PREFETCH(buf ^ 1, it * 32)
        CP_COMMIT
        G2_COMPUTE(buf)
        CP_WAIT0
        __syncthreads();
        buf ^= 1;
    }
    G2_COMPUTE(buf)

    #pragma unroll
    for (int mi = 0; mi < 4; mi++) {
        const int rA = row0 + m0 + mi * 16 + g;
        #pragma unroll
        for (int ni = 0; ni < 4; ni++) {
            const int cc = col0 + n0 + ni * 8 + 2 * t;
            const float b0 = bias[cc], b1 = bias[cc + 1];
            float2 o0 = { acc[mi][ni][0] + b0, acc[mi][ni][1] + b1 };
            float2 o1 = { acc[mi][ni][2] + b0, acc[mi][ni][3] + b1 };
            *(float2*)&C[(size_t)rA * N + cc] = o0;
            *(float2*)&C[(size_t)(rA + 8) * N + cc] = o1;
        }
    }
}

// ============================================================
// qrel[bh, t, r] = SCALE * sum_j q[t,b,h*64+j] * rpk[r, j]
// ============================================================
__global__ void __launch_bounds__(128)
qrel_kernel(const float* __restrict__ rpk) {
    const int t = blockIdx.x;
    const int bh = blockIdx.y;
    const int b = bh >> 4, h = bh & 15;
    __shared__ float qs[HD];
    __shared__ float rs[NR * HD];
    const int tid = threadIdx.x;
    if (tid < HD)
        qs[tid] = g_qkv[(size_t)t * BSZ * E3 + (size_t)b * E3 + h * HD + tid] * SCALE;
    for (int i = tid; i < NR * HD; i += 128) rs[i] = rpk[i];
    __syncthreads();
    if (tid < NR) {
        float s = 0.f;
        #pragma unroll
        for (int j = 0; j < HD; j++) s += qs[j] * rs[tid * HD + j];
        g_qrel[((size_t)bh * T_SEQ + t) * NR + tid] = s;
    }
}

// ============================================================
// scores_tc: scores = (SCALE*q)·k + qrel lookup; ldmatrix frags.
// ============================================================
#define SC_ROW 36
#define SC_BUF (128 * SC_ROW)

__global__ void __launch_bounds__(256, 2)
scores_tc() {
    extern __shared__ uint32_t sm[];
    uint32_t* Qh = sm;
    uint32_t* Ql = sm + SC_BUF;
    uint32_t* Kh = sm + 2 * SC_BUF;
    uint32_t* Kl = sm + 3 * SC_BUF;

    const int bh = blockIdx.z;
    const int b = bh >> 4, h = bh & 15;
    const int t0 = blockIdx.y * 128, s0 = blockIdx.x * 128;
    const int tid = threadIdx.x;
    const int warp = tid >> 5, lane = tid & 31;
    const int g = lane >> 2, t = lane & 3;
    const int m0 = (warp >> 2) * 64;
    const int n0 = (warp & 3) * 32;
    const size_t qoff = (size_t)b * E3 + h * HD;

    const uint32_t smb = smem_u32(sm);
    const int a_loff = (lane & 15) * SC_ROW + (lane >> 4) * 4;
    const int b_loff = (((lane >> 4) << 3) + (lane & 7)) * SC_ROW + ((lane >> 3) & 1) * 4;

    #pragma unroll
    for (int i = 0; i < 8; i++) {
        int f = tid + i * 256;
        int row = f >> 4;
        int c = (f & 15) * 4;
        float4 q = *(const float4*)&g_qkv[(size_t)(t0 + row) * BSZ * E3 + qoff + c];
        float4 k = *(const float4*)&g_qkv[(size_t)(s0 + row) * BSZ * E3 + qoff + EMB + c];
        int base = row * SC_ROW + (c >> 1);
        uint32_t h0, l0, h1, l1;
        split_pair(q.x * SCALE, q.y * SCALE, h0, l0);
        split_pair(q.z * SCALE, q.w * SCALE, h1, l1);
        Qh[base] = h0; Qh[base + 1] = h1;
        Ql[base] = l0; Ql[base + 1] = l1;
        split_pair(k.x, k.y, h0, l0);
        split_pair(k.z, k.w, h1, l1);
        Kh[base] = h0; Kh[base + 1] = h1;
        Kl[base] = l0; Kl[base + 1] = l1;
    }
    __syncthreads();

    float acc[4][4][4] = {};
    #pragma unroll
    for (int kc = 0; kc < 32; kc += 8) {
        uint32_t bhf[4][2], blf[4][2];
        #pragma unroll
        for (int np = 0; np < 2; np++) {
            uint32_t aw = smb + 4u * (2 * SC_BUF + (n0 + np * 16) * SC_ROW + kc + b_loff);
            LDSM4(bhf[2*np][0], bhf[2*np][1], bhf[2*np+1][0], bhf[2*np+1][1], aw)
            LDSM4(blf[2*np][0], blf[2*np][1], blf[2*np+1][0], blf[2*np+1][1],
                  aw + 4u * SC_BUF)
        }
        #pragma unroll
        for (int mi = 0; mi < 4; mi++) {
            uint32_t ah[4], al[4];
            uint32_t aa = smb + 4u * ((m0 + mi * 16) * SC_ROW + kc + a_loff);
            LDSM4(ah[0], ah[1], ah[2], ah[3], aa)
            LDSM4(al[0], al[1], al[2], al[3], aa + 4u * SC_BUF)
            #pragma unroll
            for (int ni = 0; ni < 4; ni++) {
                MMA16816(acc[mi][ni], ah, bhf[ni])
                MMA16816(acc[mi][ni], ah, blf[ni])
                MMA16816(acc[mi][ni], al, bhf[ni])
            }
        }
    }

    #pragma unroll
    for (int mi = 0; mi < 4; mi++) {
        #pragma unroll
        for (int rr = 0; rr < 2; rr++) {
            const int tI = t0 + m0 + mi * 16 + g + rr * 8;
            const float* qr_row = &g_qrel[((size_t)bh * T_SEQ + tI) * NR];
            float* orow = &g_scores[((size_t)bh * T_SEQ + tI) * T_SEQ];
            #pragma unroll
            for (int ni = 0; ni < 4; ni++) {
                const int sI = s0 + n0 + ni * 8 + 2 * t;
                int d0 = sI - tI;     d0 = d0 < -16 ? -16 : (d0 > 16 ? 16 : d0);
                int d1 = sI + 1 - tI; d1 = d1 < -16 ? -16 : (d1 > 16 ? 16 : d1);
                float2 o;
                o.x = acc[mi][ni][rr * 2 + 0] + qr_row[d0 + 16];
                o.y = acc[mi][ni][rr * 2 + 1] + qr_row[d1 + 16];
                *(float2*)&orow[sI] = o;
            }
        }
    }
}

// ============================================================
// Fused softmax + avg; writes P as SPLIT bf16x2 hi/lo.
// ============================================================
#define SMPAD 1028
__global__ void __launch_bounds__(256)
softmax_avg_kernel(float* __restrict__ avg) {
    extern __shared__ float S[];
    const int t = blockIdx.x;
    const int b = blockIdx.y;
    const int tid = threadIdx.x;
    const int warp = tid >> 5, lane = tid & 31;

    #pragma unroll
    for (int rep = 0; rep < 2; rep++) {
        const int h = warp + rep * 8;
        const size_t prow = ((size_t)(b * NH + h)) * T_SEQ + t;
        const float* row = g_scores + prow * T_SEQ;
        float4 v[8];
        #pragma unroll
        for (int i = 0; i < 8; i++)
            v[i] = *(const float4*)&row[lane * 4 + i * 128];

        float m = -1e30f;
        #pragma unroll
        for (int i = 0; i < 8; i++)
            m = fmaxf(m, fmaxf(fmaxf(v[i].x, v[i].y), fmaxf(v[i].z, v[i].w)));
        #pragma unroll
        for (int o = 16; o; o >>= 1) m = fmaxf(m, __shfl_xor_sync(0xffffffffu, m, o));

        float ssum = 0.f;
        #pragma unroll
        for (int i = 0; i < 8; i++) {
            v[i].x = __expf(v[i].x - m); v[i].y = __expf(v[i].y - m);
            v[i].z = __expf(v[i].z - m); v[i].w = __expf(v[i].w - m);
            ssum += v[i].x + v[i].y + v[i].z + v[i].w;
        }
        #pragma unroll
        for (int o = 16; o; o >>= 1) ssum += __shfl_xor_sync(0xffffffffu, ssum, o);
        const float inv = 1.0f / ssum;

        float* srow = &S[(size_t)h * SMPAD];
        uint32_t* ph = g_ph + prow * 512;
        uint32_t* pl = g_pl + prow * 512;
        #pragma unroll
        for (int i = 0; i < 8; i++) {
            v[i].x *= inv; v[i].y *= inv; v[i].z *= inv; v[i].w *= inv;
            *(float4*)&srow[lane * 4 + i * 128] = v[i];
            uint32_t h0, l0, h1, l1;
            split_pair(v[i].x, v[i].y, h0, l0);
            split_pair(v[i].z, v[i].w, h1, l1);
            uint2 ho = {h0, h1}, lo = {l0, l1};
            *(uint2*)&ph[lane * 2 + i * 64] = ho;
            *(uint2*)&pl[lane * 2 + i * 64] = lo;
        }
    }
    __syncthreads();

    const int c = tid * 4;
    float4 acc = make_float4(0.f, 0.f, 0.f, 0.f);
    #pragma unroll
    for (int h = 0; h < NH; h++) {
        float4 v = *(const float4*)&S[(size_t)h * SMPAD + c];
        acc.x += v.x; acc.y += v.y; acc.z += v.z; acc.w += v.w;
    }
    const float invh = 1.0f / NH;
    acc.x *= invh; acc.y *= invh; acc.z *= invh; acc.w *= invh;
    *(float4*)&avg[(((size_t)b * T_SEQ + t) * T_SEQ) + c] = acc;
}

// ============================================================
// pv_tc2: attn = P @ V, pre-split inputs, cp.async + ldmatrix.
// ============================================================
#define PV_ROW 20
#define PV_PB (128 * PV_ROW)
#define PV_VB (64 * PV_ROW)

__global__ void __launch_bounds__(256, 2)
pv_tc2() {
    extern __shared__ uint32_t sm[];

    const int bh = blockIdx.z;
    const int b = bh >> 4, h = bh & 15;
    const int t0 = blockIdx.x * 128;
    const int tid = threadIdx.x;
    const int warp = tid >> 5, lane = tid & 31;
    const int g = lane >> 2, t = lane & 3;
    const int m0 = (warp >> 1) * 32;
    const int n0 = (warp & 1) * 32;

    const uint32_t* phg = g_ph + ((size_t)bh * T_SEQ + t0) * 512;
    const uint32_t* plg = g_pl + ((size_t)bh * T_SEQ + t0) * 512;
    const uint32_t* vhg = g_vth + (size_t)bh * 64 * 512;
    const uint32_t* vlg = g_vtl + (size_t)bh * 64 * 512;

    const uint32_t smb = smem_u32(sm);
    const int a_loff = (lane & 15) * PV_ROW + (lane >> 4) * 4;
    const int b_loff = (((lane >> 4) << 3) + (lane & 7)) * PV_ROW + ((lane >> 3) & 1) * 4;

    int prow[2], pcol[2];
    #pragma unroll
    for (int i = 0; i < 2; i++) {
        int f = tid + i * 256;
        prow[i] = f >> 2;
        pcol[i] = (f & 3) * 4;
    }
    const int vrow = tid >> 2;
    const int vcol = (tid & 3) * 4;

#define P2_PREFETCH(bf, sp0)                                                   \
    _Pragma("unroll")                                                          \
    for (int i = 0; i < 2; i++) {                                              \
        size_t idx = (size_t)prow[i] * 512 + (sp0) + pcol[i];                  \
        uint32_t sb = smb + 4u * ((bf) * PV_PB + prow[i] * PV_ROW + pcol[i]);  \
        CP_ASYNC16(sb,                   phg + idx)                            \
        CP_ASYNC16(sb + 4u * 2 * PV_PB,  plg + idx)                            \
    }                                                                          \
    {                                                                          \
        size_t idx = (size_t)vrow * 512 + (sp0) + vcol;                        \
        uint32_t sb = smb + 4u * (4 * PV_PB + (bf) * PV_VB + vrow * PV_ROW + vcol); \
        CP_ASYNC16(sb,                   vhg + idx)                            \
        CP_ASYNC16(sb + 4u * 2 * PV_VB,  vlg + idx)                            \
    }

    float acc[2][4][4] = {};

#define P2_COMPUTE(bf)                                                         \
    _Pragma("unroll")                                                          \
    for (int ks = 0; ks < 2; ks++) {                                           \
        const int kc = ks * 8;                                                 \
        uint32_t bhf[4][2], blf[4][2];                                         \
        _Pragma("unroll")                                                      \
        for (int np = 0; np < 2; np++) {                                       \
            uint32_t aw = smb + 4u * (4 * PV_PB + (bf) * PV_VB                 \
                        + (n0 + np * 16) * PV_ROW + kc + b_loff);              \
            LDSM4(bhf[2*np][0], bhf[2*np][1], bhf[2*np+1][0], bhf[2*np+1][1], aw) \
            LDSM4(blf[2*np][0], blf[2*np][1], blf[2*np+1][0], blf[2*np+1][1],  \
                  aw + 4u * 2 * PV_VB)                                         \
        }                                                                      \
        _Pragma("unroll")                                                      \
        for (int mi = 0; mi < 2; mi++) {                                       \
            uint32_t ah[4], al[4];                                             \
            uint32_t aa = smb + 4u * ((bf) * PV_PB                             \
                        + (m0 + mi * 16) * PV_ROW + kc + a_loff);              \
            LDSM4(ah[0], ah[1], ah[2], ah[3], aa)                              \
            LDSM4(al[0], al[1], al[2], al[3], aa + 4u * 2 * PV_PB)             \
            _Pragma("unroll")                                                  \
            for (int ni = 0; ni < 4; ni++) {                                   \
                MMA16816(acc[mi][ni], ah, bhf[ni])                             \
                MMA16816(acc[mi][ni], ah, blf[ni])                             \
                MMA16816(acc[mi][ni], al, bhf[ni])                             \
            }                                                                  \
        }                                                                      \
    }

    P2_PREFETCH(0, 0)
    CP_COMMIT
    CP_WAIT0
    __syncthreads();
    int buf = 0;
    for (int it = 1; it < 32; it++) {
        P2_PREFETCH(buf ^ 1, it * 16)
        CP_COMMIT
        P2_COMPUTE(buf)
        CP_WAIT0
        __syncthreads();
        buf ^= 1;
    }
    P2_COMPUTE(buf)

    #pragma unroll
    for (int mi = 0; mi < 2; mi++) {
        const int rA = t0 + m0 + mi * 16 + g;
        #pragma unroll
        for (int ni = 0; ni < 4; ni++) {
            const int cc = n0 + ni * 8 + 2 * t;
            const size_t o0i = (size_t)rA * (BSZ * EMB / 2) + b * (EMB / 2) + ((h * HD + cc) >> 1);
            const size_t o1i = (size_t)(rA + 8) * (BSZ * EMB / 2) + b * (EMB / 2) + ((h * HD + cc) >> 1);
            uint32_t hh, ll;
            split_pair(acc[mi][ni][0], acc[mi][ni][1], hh, ll);
            g_ath[o0i] = hh; g_atl[o0i] = ll;
            split_pair(acc[mi][ni][2], acc[mi][ni][3], hh, ll);
            g_ath[o1i] = hh; g_atl[o1i] = ll;
        }
    }
}

// ============================================================
extern "C" void kernel_launch(void* const* d_in, const int* in_sizes, int n_in,
                              void* d_out, int out_size) {
    const float* query = (const float*)d_in[0];
    const float* w_in  = (const float*)d_in[1];
    const float* b_in  = (const float*)d_in[2];
    const float* w_out = (const float*)d_in[3];
    const float* b_out = (const float*)d_in[4];
    const float* rpk   = (const float*)d_in[5];
    float* out = (float*)d_out;

    void *pv_;
    float* p_qkv;   cudaGetSymbolAddress(&pv_, g_qkv);  p_qkv = (float*)pv_;
    uint32_t *qh, *ql, *wih, *wil, *woh, *wol, *ath, *atl;
    cudaGetSymbolAddress(&pv_, g_qh);  qh  = (uint32_t*)pv_;
    cudaGetSymbolAddress(&pv_, g_ql);  ql  = (uint32_t*)pv_;
    cudaGetSymbolAddress(&pv_, g_wih); wih = (uint32_t*)pv_;
    cudaGetSymbolAddress(&pv_, g_wil); wil = (uint32_t*)pv_;
    cudaGetSymbolAddress(&pv_, g_woh); woh = (uint32_t*)pv_;
    cudaGetSymbolAddress(&pv_, g_wol); wol = (uint32_t*)pv_;
    cudaGetSymbolAddress(&pv_, g_ath); ath = (uint32_t*)pv_;
    cudaGetSymbolAddress(&pv_, g_atl); atl = (uint32_t*)pv_;

    const int gemm_smem   = 8 * GT_BUF * sizeof(uint32_t);    // 81920
    const int scores_smem = 4 * SC_BUF * sizeof(uint32_t);    // 73728
    const int smax_smem   = 16 * SMPAD * sizeof(float);       // 65792
    const int pv_smem     = (4 * PV_PB + 4 * PV_VB) * sizeof(uint32_t);  // 61440
    cudaFuncSetAttribute(gemm_tc2, cudaFuncAttributeMaxDynamicSharedMemorySize, gemm_smem);
    cudaFuncSetAttribute(scores_tc, cudaFuncAttributeMaxDynamicSharedMemorySize, scores_smem);
    cudaFuncSetAttribute(softmax_avg_kernel, cudaFuncAttributeMaxDynamicSharedMemorySize, smax_smem);
    cudaFuncSetAttribute(pv_tc2, cudaFuncAttributeMaxDynamicSharedMemorySize, pv_smem);

    // 0. pre-split inputs / weights
    split_lin<<<8192, 256>>>(query, qh, ql);
    split_lin<<<3072, 256>>>(w_in, wih, wil);
    split_lin<<<1024, 256>>>(w_out, woh, wol);

    // 1. QKV projection
    {
        dim3 grid(E3 / 128, (T_SEQ * BSZ) / 128);
        gemm_tc2<<<grid, 256, gemm_smem>>>(qh, ql, wih, wil, b_in, p_qkv,
                                           T_SEQ * BSZ, E3, EMB);
    }
    // 2. qrel table + V transpose/split
    {
        dim3 grid(T_SEQ, BH);
        qrel_kernel<<<grid, 128>>>(rpk);
    }
    {
        dim3 grid(T_SEQ / 64, BH);
        vt_split<<<grid, 256>>>();
    }
    // 3. scores
    {
        dim3 grid(T_SEQ / 128, T_SEQ / 128, BH);
        scores_tc<<<grid, 256, scores_smem>>>();
    }
    // 4. softmax -> split P + avg weights
    {
        dim3 grid(T_SEQ, BSZ);
        softmax_avg_kernel<<<grid, 256, smax_smem>>>(out + (size_t)T_SEQ * BSZ * EMB);
    }
    // 5. attn = P @ V -> split attn
    {
        dim3 grid(T_SEQ / 128, 1, BH);
        pv_tc2<<<grid, 256, pv_smem>>>();
    }
    // 6. out projection
    {
        dim3 grid(EMB / 128, (T_SEQ * BSZ) / 128);
        gemm_tc2<<<grid, 256, gemm_smem>>>(ath, atl, woh, wol, b_out, out,
                                           T_SEQ * BSZ, EMB, EMB);
    }
}